// round 5
// baseline (speedup 1.0000x reference)
#include <cuda_runtime.h>
#include <math.h>
#include <stdint.h>

// Problem dims
constexpr int Bc = 4, Sc = 2048, Dc = 2048, Hc = 16, HDc = 128;
constexpr int Mc = Bc * Sc;

// Scratch
__device__ float g_Q[Bc * Hc * Sc * HDc];  // [B,H,S,HD]
__device__ float g_K[Bc * Hc * Sc * HDc];  // [B,H,S,HD]
__device__ float g_V[Bc * Hc * Sc * HDc];  // [B,H,S,HD]
__device__ float g_O[Bc * Sc * Dc];        // [B,S,D]

// ---------------------------------------------------------------------------
// helpers (sm_103 base target only: no tcgen05 / no 'a'-suffix features)
// ---------------------------------------------------------------------------
__device__ __forceinline__ float tf32_rn(float x) {
    uint32_t u;
    asm("cvt.rna.tf32.f32 %0, %1;" : "=r"(u) : "f"(x));
    return __uint_as_float(u);
}
__device__ __forceinline__ uint32_t tf32_rn_u(float x) {
    uint32_t u;
    asm("cvt.rna.tf32.f32 %0, %1;" : "=r"(u) : "f"(x));
    return u;
}

__device__ __forceinline__ void mma_tf32(float* d, const uint32_t* a, const uint32_t* b) {
    asm volatile(
        "mma.sync.aligned.m16n8k8.row.col.f32.tf32.tf32.f32 "
        "{%0,%1,%2,%3},{%4,%5,%6,%7},{%8,%9},{%0,%1,%2,%3};"
        : "+f"(d[0]), "+f"(d[1]), "+f"(d[2]), "+f"(d[3])
        : "r"(a[0]), "r"(a[1]), "r"(a[2]), "r"(a[3]), "r"(b[0]), "r"(b[1]));
}

__device__ __forceinline__ uint32_t smem_u32(const void* p) {
    uint32_t a;
    asm("{ .reg .u64 t; cvta.to.shared.u64 t, %1; cvt.u32.u64 %0, t; }"
        : "=r"(a) : "l"(p));
    return a;
}

#define CP_ASYNC16(dst, src) \
    asm volatile("cp.async.cg.shared.global [%0], [%1], 16;" :: "r"(dst), "l"(src))
#define CP_COMMIT() asm volatile("cp.async.commit_group;" ::: "memory")
#define CP_WAIT1()  asm volatile("cp.async.wait_group 1;" ::: "memory")

// ---------------------------------------------------------------------------
// GEMM: C[M,N] = A[M,K] * W[N,K]^T via tf32 mma.sync, cp.async 3-stage ring.
// CTA tile 128x128x32; 8 warps, warp tile 64x32 (4x4 m16n8k8).
// smem per stage: A 128x36 + B 128x36 floats (padded; frag reads conflict-free).
// tf32 rounding applied at fragment load (bit-identical to store-side rounding).
// MODE 0: row-major [M,N]; MODE 1: scatter [B,H,S,HD]; MODE 2: +RoPE.
// ---------------------------------------------------------------------------
constexpr int LDSg   = 36;
constexpr int GST    = 3;
constexpr int STAGEF = 2 * 128 * LDSg;                 // floats per stage (A+B)
constexpr int GSMEM  = GST * STAGEF * (int)sizeof(float);  // 110,592 B

template <int MODE>
__global__ void __launch_bounds__(256, 2)
gemm_tf32(const float* __restrict__ A, const float* __restrict__ W,
          float* __restrict__ out, const int* __restrict__ pos)
{
    extern __shared__ float smf[];
    constexpr int Kd = Dc;
    constexpr int Nd = Dc;

    const int tid  = threadIdx.x;
    const int bm   = blockIdx.y * 128;
    const int bn   = blockIdx.x * 128;
    const int wid  = tid >> 5;
    const int lane = tid & 31;
    const int wm   = (wid >> 2) * 64;
    const int wn   = (wid & 3) * 32;
    const int g    = lane >> 2;
    const int t4   = lane & 3;

    // loader: rows {lr, lr+32, lr+64, lr+96}, float4 slot lc within 32-wide ktile
    const int lr = tid >> 3;
    const int lc = (tid & 7) * 4;
    const float* Ag = A + (size_t)(bm + lr) * Kd + lc;
    const float* Wg = W + (size_t)(bn + lr) * Kd + lc;
    const uint32_t smb = smem_u32(smf);
    const uint32_t dstA = smb + (uint32_t)(lr * LDSg + lc) * 4u;
    const uint32_t dstB = dstA + (uint32_t)(128 * LDSg) * 4u;

    auto issue_stage = [&](int s, int kt) {
        const uint32_t so = (uint32_t)(s * STAGEF) * 4u;
        const int ko = kt * 32;
#pragma unroll
        for (int p = 0; p < 4; p++) {
            const uint32_t ro = (uint32_t)(p * 32 * LDSg) * 4u;
            CP_ASYNC16(dstA + so + ro, Ag + (size_t)p * 32 * Kd + ko);
            CP_ASYNC16(dstB + so + ro, Wg + (size_t)p * 32 * Kd + ko);
        }
    };

    float acc[4][4][4];
#pragma unroll
    for (int mt = 0; mt < 4; mt++)
#pragma unroll
        for (int nt = 0; nt < 4; nt++)
#pragma unroll
            for (int r = 0; r < 4; r++) acc[mt][nt][r] = 0.0f;

    issue_stage(0, 0); CP_COMMIT();
    issue_stage(1, 1); CP_COMMIT();

    constexpr int NKT = Kd / 32;  // 64
    for (int kt = 0; kt < NKT; kt++) {
        const int s = kt % GST;
        CP_WAIT1();
        __syncthreads();
        if (kt + 2 < NKT) issue_stage((kt + 2) % GST, kt + 2);
        CP_COMMIT();

        const float* As = smf + s * STAGEF;
        const float* Bs = As + 128 * LDSg;
#pragma unroll
        for (int ks = 0; ks < 4; ks++) {
            const int k0 = ks * 8;
            uint32_t af[4][4], bf[4][2];
#pragma unroll
            for (int mt = 0; mt < 4; mt++) {
                const int r0 = (wm + mt * 16 + g) * LDSg + k0 + t4;
                af[mt][0] = tf32_rn_u(As[r0]);
                af[mt][1] = tf32_rn_u(As[r0 + 8 * LDSg]);
                af[mt][2] = tf32_rn_u(As[r0 + 4]);
                af[mt][3] = tf32_rn_u(As[r0 + 8 * LDSg + 4]);
            }
#pragma unroll
            for (int nt = 0; nt < 4; nt++) {
                const int c0 = (wn + nt * 8 + g) * LDSg + k0 + t4;
                bf[nt][0] = tf32_rn_u(Bs[c0]);
                bf[nt][1] = tf32_rn_u(Bs[c0 + 4]);
            }
#pragma unroll
            for (int mt = 0; mt < 4; mt++)
#pragma unroll
                for (int nt = 0; nt < 4; nt++)
                    mma_tf32(acc[mt][nt], af[mt], bf[nt]);
        }
    }

    // Epilogue: thread holds rows (g, g+8), col pair (2t4, 2t4+1) per 16x8 tile.
#pragma unroll
    for (int nt = 0; nt < 4; nt++) {
        const int col = bn + wn + nt * 8 + 2 * t4;
        if (MODE == 0) {
#pragma unroll
            for (int mt = 0; mt < 4; mt++) {
                const int r0 = bm + wm + mt * 16 + g;
                *(float2*)&out[(size_t)r0 * Nd + col] =
                    make_float2(acc[mt][nt][0], acc[mt][nt][1]);
                *(float2*)&out[(size_t)(r0 + 8) * Nd + col] =
                    make_float2(acc[mt][nt][2], acc[mt][nt][3]);
            }
        } else {
            const int h  = col >> 7;
            const int hd = col & 127;
            float invf = 0.0f;
            if (MODE == 2)
                invf = (float)exp2(-(double)hd * (13.287712379549449 / 128.0));
#pragma unroll
            for (int mt = 0; mt < 4; mt++) {
#pragma unroll
                for (int rr = 0; rr < 2; rr++) {
                    const int m = bm + wm + mt * 16 + g + rr * 8;
                    const int b = m >> 11;
                    const int s = m & 2047;
                    float x1 = acc[mt][nt][rr * 2];
                    float x2 = acc[mt][nt][rr * 2 + 1];
                    float r1 = x1, r2 = x2;
                    if (MODE == 2) {
                        const float ang = (float)pos[s] * invf;
                        float sn, cs;
                        sincosf(ang, &sn, &cs);
                        r1 = x1 * cs - x2 * sn;
                        r2 = x1 * sn + x2 * cs;
                    }
                    *(float2*)&out[(((size_t)b * Hc + h) * Sc + s) * HDc + hd] =
                        make_float2(r1, r2);
                }
            }
        }
    }
}

// ---------------------------------------------------------------------------
// Flash attention (causal) via tf32 mma.sync — unchanged from round 3.
// ---------------------------------------------------------------------------
__global__ void __launch_bounds__(256, 1)
attn_mma(const float* __restrict__ Q, const float* __restrict__ K,
         const float* __restrict__ V, float* __restrict__ O)
{
    extern __shared__ float smf[];
    float* Qs = smf;                 // 128 x 132
    float* Ks = Qs + 128 * 132;      // 64 x 132
    float* Vs = Ks + 64 * 132;       // 64 x 136
    float* Ps = Vs + 64 * 136;       // 128 x 68

    const int tid  = threadIdx.x;
    const int wid  = tid >> 5;
    const int lane = tid & 31;
    const int g    = lane >> 2;
    const int t4   = lane & 3;
    const int qb   = (gridDim.x - 1) - blockIdx.x;
    const int bh   = blockIdx.y;
    const int q0   = qb * 128;
    const size_t hoff = (size_t)bh * (size_t)(Sc * HDc);
    const float scale = 0.08838834764831845f;

    const float* Qg = Q + hoff + (size_t)q0 * HDc;
    for (int i = tid; i < 128 * 32; i += 256) {
        int r = i >> 5, c = (i & 31) * 4;
        float4 v = *(const float4*)(Qg + (size_t)r * HDc + c);
        float* qs = &Qs[r * 132 + c];
        qs[0] = tf32_rn(v.x * scale); qs[1] = tf32_rn(v.y * scale);
        qs[2] = tf32_rn(v.z * scale); qs[3] = tf32_rn(v.w * scale);
    }

    float accO[16][4];
#pragma unroll
    for (int nt = 0; nt < 16; nt++)
#pragma unroll
        for (int r = 0; r < 4; r++) accO[nt][r] = 0.0f;
    float m0 = -1e30f, m1 = -1e30f, l0 = 0.0f, l1 = 0.0f;
    __syncthreads();

    const int rowb = wid * 16;
    const int nkb = 2 * qb + 2;
    for (int kb = 0; kb < nkb; kb++) {
        const float* Kg = K + hoff + (size_t)(kb * 64) * HDc;
        const float* Vg = V + hoff + (size_t)(kb * 64) * HDc;
        for (int i = tid; i < 64 * 32; i += 256) {
            int r = i >> 5, c = (i & 31) * 4;
            float4 kv = *(const float4*)(Kg + (size_t)r * HDc + c);
            float* ks = &Ks[r * 132 + c];
            ks[0] = tf32_rn(kv.x); ks[1] = tf32_rn(kv.y);
            ks[2] = tf32_rn(kv.z); ks[3] = tf32_rn(kv.w);
            float4 vv = *(const float4*)(Vg + (size_t)r * HDc + c);
            float* vs = &Vs[r * 136 + c];
            vs[0] = tf32_rn(vv.x); vs[1] = tf32_rn(vv.y);
            vs[2] = tf32_rn(vv.z); vs[3] = tf32_rn(vv.w);
        }
        __syncthreads();

        float s[8][4];
#pragma unroll
        for (int nt = 0; nt < 8; nt++)
#pragma unroll
            for (int r = 0; r < 4; r++) s[nt][r] = 0.0f;

#pragma unroll
        for (int ks_ = 0; ks_ < 16; ks_++) {
            const int k0 = ks_ * 8;
            uint32_t a[4];
            const int r0 = (rowb + g) * 132 + k0 + t4;
            a[0] = __float_as_uint(Qs[r0]);
            a[1] = __float_as_uint(Qs[r0 + 8 * 132]);
            a[2] = __float_as_uint(Qs[r0 + 4]);
            a[3] = __float_as_uint(Qs[r0 + 8 * 132 + 4]);
#pragma unroll
            for (int nt = 0; nt < 8; nt++) {
                uint32_t b[2];
                const int c0 = (nt * 8 + g) * 132 + k0 + t4;
                b[0] = __float_as_uint(Ks[c0]);
                b[1] = __float_as_uint(Ks[c0 + 4]);
                mma_tf32(s[nt], a, b);
            }
        }

        if (kb >= 2 * qb) {
            const int colb = kb * 64 + 2 * t4;
            const int row0 = q0 + rowb + g;
#pragma unroll
            for (int nt = 0; nt < 8; nt++) {
                const int c0 = colb + nt * 8;
                if (c0     > row0)     s[nt][0] = -1e30f;
                if (c0 + 1 > row0)     s[nt][1] = -1e30f;
                if (c0     > row0 + 8) s[nt][2] = -1e30f;
                if (c0 + 1 > row0 + 8) s[nt][3] = -1e30f;
            }
        }

        float bm0 = -1e30f, bm1 = -1e30f;
#pragma unroll
        for (int nt = 0; nt < 8; nt++) {
            bm0 = fmaxf(bm0, fmaxf(s[nt][0], s[nt][1]));
            bm1 = fmaxf(bm1, fmaxf(s[nt][2], s[nt][3]));
        }
        bm0 = fmaxf(bm0, __shfl_xor_sync(0xffffffffu, bm0, 1));
        bm0 = fmaxf(bm0, __shfl_xor_sync(0xffffffffu, bm0, 2));
        bm1 = fmaxf(bm1, __shfl_xor_sync(0xffffffffu, bm1, 1));
        bm1 = fmaxf(bm1, __shfl_xor_sync(0xffffffffu, bm1, 2));
        const float nm0 = fmaxf(m0, bm0);
        const float nm1 = fmaxf(m1, bm1);
        const float f0 = __expf(m0 - nm0);
        const float f1 = __expf(m1 - nm1);
        float ps0 = 0.0f, ps1 = 0.0f;
#pragma unroll
        for (int nt = 0; nt < 8; nt++) {
            float p0 = tf32_rn(__expf(s[nt][0] - nm0));
            float p1 = tf32_rn(__expf(s[nt][1] - nm0));
            float p2 = tf32_rn(__expf(s[nt][2] - nm1));
            float p3 = tf32_rn(__expf(s[nt][3] - nm1));
            ps0 += p0 + p1;
            ps1 += p2 + p3;
            const int cc = nt * 8 + 2 * t4;
            *(float2*)&Ps[(rowb + g) * 68 + cc]     = make_float2(p0, p1);
            *(float2*)&Ps[(rowb + g + 8) * 68 + cc] = make_float2(p2, p3);
        }
        ps0 += __shfl_xor_sync(0xffffffffu, ps0, 1);
        ps0 += __shfl_xor_sync(0xffffffffu, ps0, 2);
        ps1 += __shfl_xor_sync(0xffffffffu, ps1, 1);
        ps1 += __shfl_xor_sync(0xffffffffu, ps1, 2);
        l0 = l0 * f0 + ps0;
        l1 = l1 * f1 + ps1;
        m0 = nm0;
        m1 = nm1;
#pragma unroll
        for (int nt = 0; nt < 16; nt++) {
            accO[nt][0] *= f0; accO[nt][1] *= f0;
            accO[nt][2] *= f1; accO[nt][3] *= f1;
        }
        __syncwarp();

#pragma unroll
        for (int ks_ = 0; ks_ < 8; ks_++) {
            const int k0 = ks_ * 8;
            uint32_t a[4];
            const int r0 = (rowb + g) * 68 + k0 + t4;
            a[0] = __float_as_uint(Ps[r0]);
            a[1] = __float_as_uint(Ps[r0 + 8 * 68]);
            a[2] = __float_as_uint(Ps[r0 + 4]);
            a[3] = __float_as_uint(Ps[r0 + 8 * 68 + 4]);
#pragma unroll
            for (int nt = 0; nt < 16; nt++) {
                uint32_t b[2];
                const int c0 = (k0 + t4) * 136 + nt * 8 + g;
                b[0] = __float_as_uint(Vs[c0]);
                b[1] = __float_as_uint(Vs[c0 + 4 * 136]);
                mma_tf32(accO[nt], a, b);
            }
        }
        __syncthreads();
    }

    const int b_ = bh >> 4;
    const int h_ = bh & 15;
    const float inv0 = 1.0f / l0;
    const float inv1 = 1.0f / l1;
    const int r0g = q0 + rowb + g;
    float* Op0 = O + ((size_t)b_ * Sc + r0g) * Dc + h_ * HDc;
    float* Op1 = Op0 + (size_t)8 * Dc;
#pragma unroll
    for (int nt = 0; nt < 16; nt++) {
        const int cc = nt * 8 + 2 * t4;
        *(float2*)&Op0[cc] = make_float2(accO[nt][0] * inv0, accO[nt][1] * inv0);
        *(float2*)&Op1[cc] = make_float2(accO[nt][2] * inv1, accO[nt][3] * inv1);
    }
}

// ---------------------------------------------------------------------------
extern "C" void kernel_launch(void* const* d_in, const int* in_sizes, int n_in,
                              void* d_out, int out_size)
{
    const float* x  = (const float*)d_in[0];
    const float* wq = (const float*)d_in[1];
    const float* wk = (const float*)d_in[2];
    const float* wv = (const float*)d_in[3];
    const float* wo = (const float*)d_in[4];
    const int* pos  = (const int*)d_in[5];

    float *q, *k, *v, *o;
    cudaGetSymbolAddress((void**)&q, g_Q);
    cudaGetSymbolAddress((void**)&k, g_K);
    cudaGetSymbolAddress((void**)&v, g_V);
    cudaGetSymbolAddress((void**)&o, g_O);

    cudaFuncSetAttribute(gemm_tf32<0>, cudaFuncAttributeMaxDynamicSharedMemorySize, GSMEM);
    cudaFuncSetAttribute(gemm_tf32<1>, cudaFuncAttributeMaxDynamicSharedMemorySize, GSMEM);
    cudaFuncSetAttribute(gemm_tf32<2>, cudaFuncAttributeMaxDynamicSharedMemorySize, GSMEM);

    dim3 gg(Dc / 128, Mc / 128);  // (16, 64)
    gemm_tf32<2><<<gg, 256, GSMEM>>>(x, wq, q, pos);   // Q proj + RoPE
    gemm_tf32<2><<<gg, 256, GSMEM>>>(x, wk, k, pos);   // K proj + RoPE
    gemm_tf32<1><<<gg, 256, GSMEM>>>(x, wv, v, pos);   // V proj

    const size_t smem = (size_t)(128 * 132 + 64 * 132 + 64 * 136 + 128 * 68) * sizeof(float);
    cudaFuncSetAttribute(attn_mma,
                         cudaFuncAttributeMaxDynamicSharedMemorySize, (int)smem);
    attn_mma<<<dim3(Sc / 128, Bc * Hc), 256, smem>>>(q, k, v, o);

    gemm_tf32<0><<<gg, 256, GSMEM>>>(o, wo, (float*)d_out, pos);  // output proj
}

// round 6
// speedup vs baseline: 1.1393x; 1.1393x over previous
#include <cuda_runtime.h>
#include <math.h>
#include <stdint.h>

// Problem dims
constexpr int Bc = 4, Sc = 2048, Dc = 2048, Hc = 16, HDc = 128;
constexpr int Mc = Bc * Sc;

// Scratch
__device__ float g_Q[Bc * Hc * Sc * HDc];  // [B,H,S,HD] tf32, pre-scaled by 1/sqrt(HD)
__device__ float g_K[Bc * Hc * Sc * HDc];  // [B,H,S,HD] tf32
__device__ float g_V[Bc * Hc * Sc * HDc];  // [B,H,S,HD] tf32
__device__ float g_O[Bc * Sc * Dc];        // [B,S,D]

// ---------------------------------------------------------------------------
// helpers (sm_103 base target: mma.sync + cp.async only)
// ---------------------------------------------------------------------------
__device__ __forceinline__ float tf32_rn(float x) {
    uint32_t u;
    asm("cvt.rna.tf32.f32 %0, %1;" : "=r"(u) : "f"(x));
    return __uint_as_float(u);
}

__device__ __forceinline__ void mma_tf32(float* d, const uint32_t* a, const uint32_t* b) {
    asm volatile(
        "mma.sync.aligned.m16n8k8.row.col.f32.tf32.tf32.f32 "
        "{%0,%1,%2,%3},{%4,%5,%6,%7},{%8,%9},{%0,%1,%2,%3};"
        : "+f"(d[0]), "+f"(d[1]), "+f"(d[2]), "+f"(d[3])
        : "r"(a[0]), "r"(a[1]), "r"(a[2]), "r"(a[3]), "r"(b[0]), "r"(b[1]));
}

__device__ __forceinline__ uint32_t smem_u32(const void* p) {
    uint32_t a;
    asm("{ .reg .u64 t; cvta.to.shared.u64 t, %1; cvt.u32.u64 %0, t; }"
        : "=r"(a) : "l"(p));
    return a;
}

#define CP_ASYNC16(dst, src) \
    asm volatile("cp.async.cg.shared.global [%0], [%1], 16;" :: "r"(dst), "l"(src))
#define CP_COMMIT() asm volatile("cp.async.commit_group;" ::: "memory")
#define CP_WAIT1()  asm volatile("cp.async.wait_group 1;" ::: "memory")
#define CP_WAIT0()  asm volatile("cp.async.wait_group 0;" ::: "memory")

// ---------------------------------------------------------------------------
// GEMM (round-3 proven form): C[M,N] = A[M,K]*W[N,K]^T via tf32 mma.sync.
// CTA 128x128x32, 8 warps, warp 64x32; store-side tf32 rounding; occupancy 2.
// MODE 0: plain fp32 [M,N]
// MODE 1: scatter [B,H,S,HD], tf32-rounded            (V)
// MODE 2: scatter + RoPE, tf32-rounded                (K)
// MODE 3: scatter + RoPE, * 1/sqrt(HD), tf32-rounded  (Q)
// ---------------------------------------------------------------------------
template <int MODE>
__global__ void __launch_bounds__(256, 2)
gemm_tf32(const float* __restrict__ A, const float* __restrict__ W,
          float* __restrict__ out, const int* __restrict__ pos)
{
    constexpr int Kd = Dc;
    constexpr int Nd = Dc;
    constexpr int LDS = 36;
    __shared__ float As[128 * LDS];
    __shared__ float Bs[128 * LDS];

    const int tid  = threadIdx.x;
    const int bm   = blockIdx.y * 128;
    const int bn   = blockIdx.x * 128;
    const int wid  = tid >> 5;
    const int lane = tid & 31;
    const int wm   = (wid >> 2) * 64;
    const int wn   = (wid & 3) * 32;
    const int g    = lane >> 2;
    const int t4   = lane & 3;

    const int lr = tid >> 3;
    const int lc = (tid & 7) * 4;
    const float* Ag = A + (size_t)(bm + lr) * Kd + lc;
    const float* Wg = W + (size_t)(bn + lr) * Kd + lc;

    float acc[4][4][4];
#pragma unroll
    for (int mt = 0; mt < 4; mt++)
#pragma unroll
        for (int nt = 0; nt < 4; nt++)
#pragma unroll
            for (int r = 0; r < 4; r++) acc[mt][nt][r] = 0.0f;

    float4 pa[4], pb[4];
#pragma unroll
    for (int p = 0; p < 4; p++) {
        pa[p] = *(const float4*)(Ag + (size_t)p * 32 * Kd);
        pb[p] = *(const float4*)(Wg + (size_t)p * 32 * Kd);
    }

    for (int kt = 0; kt < Kd; kt += 32) {
#pragma unroll
        for (int p = 0; p < 4; p++) {
            float* as = &As[(lr + p * 32) * LDS + lc];
            as[0] = tf32_rn(pa[p].x); as[1] = tf32_rn(pa[p].y);
            as[2] = tf32_rn(pa[p].z); as[3] = tf32_rn(pa[p].w);
            float* bs = &Bs[(lr + p * 32) * LDS + lc];
            bs[0] = tf32_rn(pb[p].x); bs[1] = tf32_rn(pb[p].y);
            bs[2] = tf32_rn(pb[p].z); bs[3] = tf32_rn(pb[p].w);
        }
        __syncthreads();

        if (kt + 32 < Kd) {
#pragma unroll
            for (int p = 0; p < 4; p++) {
                pa[p] = *(const float4*)(Ag + (size_t)p * 32 * Kd + kt + 32);
                pb[p] = *(const float4*)(Wg + (size_t)p * 32 * Kd + kt + 32);
            }
        }

#pragma unroll
        for (int ks = 0; ks < 4; ks++) {
            const int k0 = ks * 8;
            uint32_t af[4][4], bf[4][2];
#pragma unroll
            for (int mt = 0; mt < 4; mt++) {
                const int r0 = (wm + mt * 16 + g) * LDS + k0 + t4;
                af[mt][0] = __float_as_uint(As[r0]);
                af[mt][1] = __float_as_uint(As[r0 + 8 * LDS]);
                af[mt][2] = __float_as_uint(As[r0 + 4]);
                af[mt][3] = __float_as_uint(As[r0 + 8 * LDS + 4]);
            }
#pragma unroll
            for (int nt = 0; nt < 4; nt++) {
                const int c0 = (wn + nt * 8 + g) * LDS + k0 + t4;
                bf[nt][0] = __float_as_uint(Bs[c0]);
                bf[nt][1] = __float_as_uint(Bs[c0 + 4]);
            }
#pragma unroll
            for (int mt = 0; mt < 4; mt++)
#pragma unroll
                for (int nt = 0; nt < 4; nt++)
                    mma_tf32(acc[mt][nt], af[mt], bf[nt]);
        }
        __syncthreads();
    }

    const float qscale = 0.08838834764831845f;  // 1/sqrt(128)
#pragma unroll
    for (int nt = 0; nt < 4; nt++) {
        const int col = bn + wn + nt * 8 + 2 * t4;
        if (MODE == 0) {
#pragma unroll
            for (int mt = 0; mt < 4; mt++) {
                const int r0 = bm + wm + mt * 16 + g;
                *(float2*)&out[(size_t)r0 * Nd + col] =
                    make_float2(acc[mt][nt][0], acc[mt][nt][1]);
                *(float2*)&out[(size_t)(r0 + 8) * Nd + col] =
                    make_float2(acc[mt][nt][2], acc[mt][nt][3]);
            }
        } else {
            const int h  = col >> 7;
            const int hd = col & 127;
            float invf = 0.0f;
            if (MODE >= 2)
                invf = (float)exp2(-(double)hd * (13.287712379549449 / 128.0));
#pragma unroll
            for (int mt = 0; mt < 4; mt++) {
#pragma unroll
                for (int rr = 0; rr < 2; rr++) {
                    const int m = bm + wm + mt * 16 + g + rr * 8;
                    const int b = m >> 11;
                    const int s = m & 2047;
                    float x1 = acc[mt][nt][rr * 2];
                    float x2 = acc[mt][nt][rr * 2 + 1];
                    float r1 = x1, r2 = x2;
                    if (MODE >= 2) {
                        const float ang = (float)pos[s] * invf;
                        float sn, cs;
                        sincosf(ang, &sn, &cs);
                        r1 = x1 * cs - x2 * sn;
                        r2 = x1 * sn + x2 * cs;
                    }
                    if (MODE == 3) { r1 *= qscale; r2 *= qscale; }
                    r1 = tf32_rn(r1);
                    r2 = tf32_rn(r2);
                    *(float2*)&out[(((size_t)b * Hc + h) * Sc + s) * HDc + hd] =
                        make_float2(r1, r2);
                }
            }
        }
    }
}

// ---------------------------------------------------------------------------
// Flash attention (causal), tf32 mma.sync, cp.async 2-stage K/V pipeline.
// Inputs already tf32-rounded (Q also pre-scaled) by the projection epilogues.
// CTA: 128 q-rows x one (b,h); 8 warps x 16 rows; key tiles of 64.
// smem (floats): stage s in [s*16896, ...): K 64x128 swizzled (8192) +
//   V 64x136 padded (8704); Ps 128x64 swizzled at 33792. Total 41984 f.
// Q fragments live in registers (staged once through stage-0 region).
// ---------------------------------------------------------------------------
constexpr int KSTG      = 16896;              // floats per K/V stage
constexpr int PS_OFF    = 2 * KSTG;           // 33792
constexpr int ATT_SMEMF = PS_OFF + 128 * 64;  // 41984 floats
constexpr int ATT_SMEMB = ATT_SMEMF * 4;      // 167,936 B

__global__ void __launch_bounds__(256, 1)
attn_mma(const float* __restrict__ Q, const float* __restrict__ K,
         const float* __restrict__ V, float* __restrict__ O)
{
    extern __shared__ float smf[];
    const uint32_t smb = smem_u32(smf);

    const int tid  = threadIdx.x;
    const int wid  = tid >> 5;
    const int lane = tid & 31;
    const int g    = lane >> 2;
    const int t4   = lane & 3;
    const int qb   = (gridDim.x - 1) - blockIdx.x;   // heavy blocks first
    const int bh   = blockIdx.y;
    const int q0   = qb * 128;
    const size_t hoff = (size_t)bh * (size_t)(Sc * HDc);
    const int rowb = wid * 16;

    // ---- Stage Q (tf32, pre-scaled) into stage-0 region, swizzled stride 128
    {
        const float* Qg = Q + hoff + (size_t)q0 * HDc;
#pragma unroll
        for (int p = 0; p < 16; p++) {
            int q = tid + p * 256;          // 0..4095 float4s
            int row = q >> 5;
            int grp = q & 31;
            int sg = (grp & 24) | ((grp & 7) ^ (row & 7));
            CP_ASYNC16(smb + (uint32_t)(row * 128 + sg * 4) * 4u,
                       Qg + (size_t)row * HDc + grp * 4);
        }
        CP_COMMIT();
        CP_WAIT0();
    }
    __syncthreads();

    // ---- Extract Q fragments to registers: qf[ks][0..3]
    uint32_t qf[16][4];
#pragma unroll
    for (int ks = 0; ks < 16; ks++) {
        const int g1 = ((2 * ks) & 24) | (((2 * ks) & 7) ^ g);
        const int g2 = ((2 * ks + 1) & 24) | (((2 * ks + 1) & 7) ^ g);
        const int r0 = (rowb + g) * 128;
        const int r1 = (rowb + g + 8) * 128;
        qf[ks][0] = __float_as_uint(smf[r0 + g1 * 4 + t4]);
        qf[ks][1] = __float_as_uint(smf[r1 + g1 * 4 + t4]);
        qf[ks][2] = __float_as_uint(smf[r0 + g2 * 4 + t4]);
        qf[ks][3] = __float_as_uint(smf[r1 + g2 * 4 + t4]);
    }
    __syncthreads();

    const int nkb = 2 * qb + 2;

    auto issue = [&](int kb) {
        const int s = kb & 1;
        const float* Kg = K + hoff + (size_t)(kb * 64) * HDc;
        const float* Vg = V + hoff + (size_t)(kb * 64) * HDc;
        const uint32_t kbase = smb + (uint32_t)(s * KSTG) * 4u;
        const uint32_t vbase = kbase + 8192u * 4u;
#pragma unroll
        for (int p = 0; p < 8; p++) {
            int q = tid + p * 256;          // 0..2047 float4s
            int row = q >> 5;
            int grp = q & 31;
            int sg = (grp & 24) | ((grp & 7) ^ (row & 7));
            CP_ASYNC16(kbase + (uint32_t)(row * 128 + sg * 4) * 4u,
                       Kg + (size_t)row * HDc + grp * 4);
        }
#pragma unroll
        for (int p = 0; p < 8; p++) {
            int q = tid + p * 256;
            int row = q >> 5;
            int grp = q & 31;
            CP_ASYNC16(vbase + (uint32_t)(row * 136 + grp * 4) * 4u,
                       Vg + (size_t)row * HDc + grp * 4);
        }
    };

    float accO[16][4];
#pragma unroll
    for (int nt = 0; nt < 16; nt++)
#pragma unroll
        for (int r = 0; r < 4; r++) accO[nt][r] = 0.0f;
    float m0 = -1e30f, m1 = -1e30f, l0 = 0.0f, l1 = 0.0f;

    issue(0); CP_COMMIT();
    if (nkb > 1) issue(1);
    CP_COMMIT();

    float* Ps = smf + PS_OFF;

    for (int kb = 0; kb < nkb; kb++) {
        CP_WAIT1();
        __syncthreads();
        const float* Ksb = smf + (kb & 1) * KSTG;
        const float* Vsb = Ksb + 8192;

        // ---- Scores: warp rows [rowb, rowb+16) x 64 keys
        float s[8][4];
#pragma unroll
        for (int nt = 0; nt < 8; nt++)
#pragma unroll
            for (int r = 0; r < 4; r++) s[nt][r] = 0.0f;

#pragma unroll
        for (int ks_ = 0; ks_ < 16; ks_++) {
            const int g1 = ((2 * ks_) & 24) | (((2 * ks_) & 7) ^ g);
            const int g2 = ((2 * ks_ + 1) & 24) | (((2 * ks_ + 1) & 7) ^ g);
#pragma unroll
            for (int nt = 0; nt < 8; nt++) {
                uint32_t b[2];
                const int kr = (nt * 8 + g) * 128;
                b[0] = __float_as_uint(Ksb[kr + g1 * 4 + t4]);
                b[1] = __float_as_uint(Ksb[kr + g2 * 4 + t4]);
                mma_tf32(s[nt], qf[ks_], b);
            }
        }

        // ---- Causal mask (only diagonal tiles)
        if (kb >= 2 * qb) {
            const int colb = kb * 64 + 2 * t4;
            const int row0 = q0 + rowb + g;
#pragma unroll
            for (int nt = 0; nt < 8; nt++) {
                const int c0 = colb + nt * 8;
                if (c0     > row0)     s[nt][0] = -1e30f;
                if (c0 + 1 > row0)     s[nt][1] = -1e30f;
                if (c0     > row0 + 8) s[nt][2] = -1e30f;
                if (c0 + 1 > row0 + 8) s[nt][3] = -1e30f;
            }
        }

        // ---- Online softmax (rows g, g+8 of warp tile)
        float bm0 = -1e30f, bm1 = -1e30f;
#pragma unroll
        for (int nt = 0; nt < 8; nt++) {
            bm0 = fmaxf(bm0, fmaxf(s[nt][0], s[nt][1]));
            bm1 = fmaxf(bm1, fmaxf(s[nt][2], s[nt][3]));
        }
        bm0 = fmaxf(bm0, __shfl_xor_sync(0xffffffffu, bm0, 1));
        bm0 = fmaxf(bm0, __shfl_xor_sync(0xffffffffu, bm0, 2));
        bm1 = fmaxf(bm1, __shfl_xor_sync(0xffffffffu, bm1, 1));
        bm1 = fmaxf(bm1, __shfl_xor_sync(0xffffffffu, bm1, 2));
        const float nm0 = fmaxf(m0, bm0);
        const float nm1 = fmaxf(m1, bm1);
        const float f0 = __expf(m0 - nm0);
        const float f1 = __expf(m1 - nm1);
        float ps0 = 0.0f, ps1 = 0.0f;
        const int prow0 = (rowb + g) * 64;
        const int prow1 = (rowb + g + 8) * 64;
        const int off2  = (2 * t4) & 3;   // 0 or 2
#pragma unroll
        for (int nt = 0; nt < 8; nt++) {
            float p0 = tf32_rn(__expf(s[nt][0] - nm0));
            float p1 = tf32_rn(__expf(s[nt][1] - nm0));
            float p2 = tf32_rn(__expf(s[nt][2] - nm1));
            float p3 = tf32_rn(__expf(s[nt][3] - nm1));
            ps0 += p0 + p1;
            ps1 += p2 + p3;
            const int f4g = 2 * nt + (t4 >> 1);
            const int sg = (f4g & 8) | ((f4g & 7) ^ g);
            *(float2*)&Ps[prow0 + sg * 4 + off2] = make_float2(p0, p1);
            *(float2*)&Ps[prow1 + sg * 4 + off2] = make_float2(p2, p3);
        }
        ps0 += __shfl_xor_sync(0xffffffffu, ps0, 1);
        ps0 += __shfl_xor_sync(0xffffffffu, ps0, 2);
        ps1 += __shfl_xor_sync(0xffffffffu, ps1, 1);
        ps1 += __shfl_xor_sync(0xffffffffu, ps1, 2);
        l0 = l0 * f0 + ps0;
        l1 = l1 * f1 + ps1;
        m0 = nm0;
        m1 = nm1;
#pragma unroll
        for (int nt = 0; nt < 16; nt++) {
            accO[nt][0] *= f0; accO[nt][1] *= f0;
            accO[nt][2] *= f1; accO[nt][3] *= f1;
        }
        __syncwarp();  // Ps rows are warp-private

        // ---- PV: accO += P[16x64] * V[64x128]
#pragma unroll
        for (int ks_ = 0; ks_ < 8; ks_++) {
            uint32_t a[4];
            const int sg1 = ((2 * ks_) & 8) | (((2 * ks_) & 7) ^ g);
            const int sg2 = ((2 * ks_ + 1) & 8) | (((2 * ks_ + 1) & 7) ^ g);
            a[0] = __float_as_uint(Ps[prow0 + sg1 * 4 + t4]);
            a[1] = __float_as_uint(Ps[prow1 + sg1 * 4 + t4]);
            a[2] = __float_as_uint(Ps[prow0 + sg2 * 4 + t4]);
            a[3] = __float_as_uint(Ps[prow1 + sg2 * 4 + t4]);
            const int vr = (8 * ks_ + t4) * 136;
#pragma unroll
            for (int nt = 0; nt < 16; nt++) {
                uint32_t b[2];
                b[0] = __float_as_uint(Vsb[vr + nt * 8 + g]);
                b[1] = __float_as_uint(Vsb[vr + 4 * 136 + nt * 8 + g]);
                mma_tf32(accO[nt], a, b);
            }
        }
        __syncthreads();   // all warps done with stage (kb&1)
        if (kb + 2 < nkb) issue(kb + 2);
        CP_COMMIT();
    }

    // ---- Normalize + write O in [B,S,D]
    const int b_ = bh >> 4;
    const int h_ = bh & 15;
    const float inv0 = 1.0f / l0;
    const float inv1 = 1.0f / l1;
    const int r0g = q0 + rowb + g;
    float* Op0 = O + ((size_t)b_ * Sc + r0g) * Dc + h_ * HDc;
    float* Op1 = Op0 + (size_t)8 * Dc;
#pragma unroll
    for (int nt = 0; nt < 16; nt++) {
        const int cc = nt * 8 + 2 * t4;
        *(float2*)&Op0[cc] = make_float2(accO[nt][0] * inv0, accO[nt][1] * inv0);
        *(float2*)&Op1[cc] = make_float2(accO[nt][2] * inv1, accO[nt][3] * inv1);
    }
}

// ---------------------------------------------------------------------------
extern "C" void kernel_launch(void* const* d_in, const int* in_sizes, int n_in,
                              void* d_out, int out_size)
{
    const float* x  = (const float*)d_in[0];
    const float* wq = (const float*)d_in[1];
    const float* wk = (const float*)d_in[2];
    const float* wv = (const float*)d_in[3];
    const float* wo = (const float*)d_in[4];
    const int* pos  = (const int*)d_in[5];

    float *q, *k, *v, *o;
    cudaGetSymbolAddress((void**)&q, g_Q);
    cudaGetSymbolAddress((void**)&k, g_K);
    cudaGetSymbolAddress((void**)&v, g_V);
    cudaGetSymbolAddress((void**)&o, g_O);

    dim3 gg(Dc / 128, Mc / 128);  // (16, 64)
    gemm_tf32<3><<<gg, 256>>>(x, wq, q, pos);   // Q proj + RoPE + scale + round
    gemm_tf32<2><<<gg, 256>>>(x, wk, k, pos);   // K proj + RoPE + round
    gemm_tf32<1><<<gg, 256>>>(x, wv, v, pos);   // V proj + round

    cudaFuncSetAttribute(attn_mma,
                         cudaFuncAttributeMaxDynamicSharedMemorySize, ATT_SMEMB);
    attn_mma<<<dim3(Sc / 128, Bc * Hc), 256, ATT_SMEMB>>>(q, k, v, o);

    gemm_tf32<0><<<gg, 256>>>(o, wo, (float*)d_out, pos);  // output proj
}

// round 7
// speedup vs baseline: 1.4675x; 1.2881x over previous
#include <cuda_runtime.h>
#include <cuda_fp16.h>
#include <math.h>
#include <stdint.h>

// Problem dims
constexpr int Bc = 4, Sc = 2048, Dc = 2048, Hc = 16, HDc = 128;
constexpr int Mc = Bc * Sc;

// Scratch
__device__ float g_Q[Bc * Hc * Sc * HDc];  // [B,H,S,HD] tf32, pre-scaled by 1/sqrt(HD)
__device__ float g_K[Bc * Hc * Sc * HDc];  // [B,H,S,HD] tf32
__device__ float g_V[Bc * Hc * Sc * HDc];  // [B,H,S,HD] tf32
__device__ float g_O[Bc * Sc * Dc];        // [B,S,D]

// ---------------------------------------------------------------------------
// helpers (sm_103 base target: mma.sync + cp.async only)
// ---------------------------------------------------------------------------
__device__ __forceinline__ float tf32_rn(float x) {
    uint32_t u;
    asm("cvt.rna.tf32.f32 %0, %1;" : "=r"(u) : "f"(x));
    return __uint_as_float(u);
}

__device__ __forceinline__ void mma_tf32(float* d, const uint32_t* a, const uint32_t* b) {
    asm volatile(
        "mma.sync.aligned.m16n8k8.row.col.f32.tf32.tf32.f32 "
        "{%0,%1,%2,%3},{%4,%5,%6,%7},{%8,%9},{%0,%1,%2,%3};"
        : "+f"(d[0]), "+f"(d[1]), "+f"(d[2]), "+f"(d[3])
        : "r"(a[0]), "r"(a[1]), "r"(a[2]), "r"(a[3]), "r"(b[0]), "r"(b[1]));
}

__device__ __forceinline__ void mma_fp16(float* d, const uint32_t* a, const uint32_t* b) {
    asm volatile(
        "mma.sync.aligned.m16n8k16.row.col.f32.f16.f16.f32 "
        "{%0,%1,%2,%3},{%4,%5,%6,%7},{%8,%9},{%0,%1,%2,%3};"
        : "+f"(d[0]), "+f"(d[1]), "+f"(d[2]), "+f"(d[3])
        : "r"(a[0]), "r"(a[1]), "r"(a[2]), "r"(a[3]), "r"(b[0]), "r"(b[1]));
}

__device__ __forceinline__ uint32_t h2u(float x, float y) {
    __half2 h = __float22half2_rn(make_float2(x, y));
    return *(uint32_t*)&h;
}

__device__ __forceinline__ uint32_t smem_u32(const void* p) {
    uint32_t a;
    asm("{ .reg .u64 t; cvta.to.shared.u64 t, %1; cvt.u32.u64 %0, t; }"
        : "=r"(a) : "l"(p));
    return a;
}

#define CP_ASYNC16(dst, src) \
    asm volatile("cp.async.cg.shared.global [%0], [%1], 16;" :: "r"(dst), "l"(src))
#define CP_COMMIT() asm volatile("cp.async.commit_group;" ::: "memory")
#define CP_WAIT1()  asm volatile("cp.async.wait_group 1;" ::: "memory")
#define CP_WAIT0()  asm volatile("cp.async.wait_group 0;" ::: "memory")

// ---------------------------------------------------------------------------
// GEMM via fp16 mma.sync m16n8k16 (fp32 accumulate).
// fp16 has the SAME 10-bit mantissa as tf32 -> identical input rounding error,
// at 2x MACs per instruction.
// C[M,N] = A[M,K]*W[N,K]^T. CTA 128x128x32, 8 warps, warp 64x32.
// smem: half2 (u32) arrays, row stride 20 u32 (frag-load banks 20g+t4: all 32
// distinct). Store-side __float22half2_rn conversion (round-to-nearest).
// MODE 0: plain fp32 [M,N]
// MODE 1: scatter [B,H,S,HD], tf32-rounded            (V)
// MODE 2: scatter + RoPE, tf32-rounded                (K)
// MODE 3: scatter + RoPE, * 1/sqrt(HD), tf32-rounded  (Q)
// ---------------------------------------------------------------------------
template <int MODE>
__global__ void __launch_bounds__(256, 2)
gemm_fp16(const float* __restrict__ A, const float* __restrict__ W,
          float* __restrict__ out, const int* __restrict__ pos)
{
    constexpr int Kd = Dc;
    constexpr int Nd = Dc;
    constexpr int LDS = 20;                 // u32 (half2) per row
    __shared__ uint32_t AsU[128 * LDS];
    __shared__ uint32_t BsU[128 * LDS];

    const int tid  = threadIdx.x;
    const int bm   = blockIdx.y * 128;
    const int bn   = blockIdx.x * 128;
    const int wid  = tid >> 5;
    const int lane = tid & 31;
    const int wm   = (wid >> 2) * 64;
    const int wn   = (wid & 3) * 32;
    const int g    = lane >> 2;
    const int t4   = lane & 3;

    const int lr  = tid >> 3;               // row 0..31 (+32p)
    const int lc4 = tid & 7;                // float4 slot -> half2 slots 2*lc4, +1
    const float* Ag = A + (size_t)(bm + lr) * Kd + lc4 * 4;
    const float* Wg = W + (size_t)(bn + lr) * Kd + lc4 * 4;

    float acc[4][4][4];
#pragma unroll
    for (int mt = 0; mt < 4; mt++)
#pragma unroll
        for (int nt = 0; nt < 4; nt++)
#pragma unroll
            for (int r = 0; r < 4; r++) acc[mt][nt][r] = 0.0f;

    float4 pa[4], pb[4];
#pragma unroll
    for (int p = 0; p < 4; p++) {
        pa[p] = *(const float4*)(Ag + (size_t)p * 32 * Kd);
        pb[p] = *(const float4*)(Wg + (size_t)p * 32 * Kd);
    }

    for (int kt = 0; kt < Kd; kt += 32) {
#pragma unroll
        for (int p = 0; p < 4; p++) {
            const int ro = (lr + p * 32) * LDS + 2 * lc4;
            AsU[ro]     = h2u(pa[p].x, pa[p].y);
            AsU[ro + 1] = h2u(pa[p].z, pa[p].w);
            BsU[ro]     = h2u(pb[p].x, pb[p].y);
            BsU[ro + 1] = h2u(pb[p].z, pb[p].w);
        }
        __syncthreads();

        if (kt + 32 < Kd) {
#pragma unroll
            for (int p = 0; p < 4; p++) {
                pa[p] = *(const float4*)(Ag + (size_t)p * 32 * Kd + kt + 32);
                pb[p] = *(const float4*)(Wg + (size_t)p * 32 * Kd + kt + 32);
            }
        }

#pragma unroll
        for (int ks = 0; ks < 2; ks++) {     // two k16 steps per 32-wide tile
            const int k0 = ks * 8;           // half2 slot base
            uint32_t af[4][4], bf[4][2];
#pragma unroll
            for (int mt = 0; mt < 4; mt++) {
                const int r0 = (wm + mt * 16 + g) * LDS + k0 + t4;
                af[mt][0] = AsU[r0];                 // row g,   k-lo
                af[mt][1] = AsU[r0 + 8 * LDS];       // row g+8, k-lo
                af[mt][2] = AsU[r0 + 4];             // row g,   k-hi
                af[mt][3] = AsU[r0 + 8 * LDS + 4];   // row g+8, k-hi
            }
#pragma unroll
            for (int nt = 0; nt < 4; nt++) {
                const int c0 = (wn + nt * 8 + g) * LDS + k0 + t4;
                bf[nt][0] = BsU[c0];
                bf[nt][1] = BsU[c0 + 4];
            }
#pragma unroll
            for (int mt = 0; mt < 4; mt++)
#pragma unroll
                for (int nt = 0; nt < 4; nt++)
                    mma_fp16(acc[mt][nt], af[mt], bf[nt]);
        }
        __syncthreads();
    }

    const float qscale = 0.08838834764831845f;  // 1/sqrt(128)
#pragma unroll
    for (int nt = 0; nt < 4; nt++) {
        const int col = bn + wn + nt * 8 + 2 * t4;
        if (MODE == 0) {
#pragma unroll
            for (int mt = 0; mt < 4; mt++) {
                const int r0 = bm + wm + mt * 16 + g;
                *(float2*)&out[(size_t)r0 * Nd + col] =
                    make_float2(acc[mt][nt][0], acc[mt][nt][1]);
                *(float2*)&out[(size_t)(r0 + 8) * Nd + col] =
                    make_float2(acc[mt][nt][2], acc[mt][nt][3]);
            }
        } else {
            const int h  = col >> 7;
            const int hd = col & 127;
            float invf = 0.0f;
            if (MODE >= 2)
                invf = (float)exp2(-(double)hd * (13.287712379549449 / 128.0));
#pragma unroll
            for (int mt = 0; mt < 4; mt++) {
#pragma unroll
                for (int rr = 0; rr < 2; rr++) {
                    const int m = bm + wm + mt * 16 + g + rr * 8;
                    const int b = m >> 11;
                    const int s = m & 2047;
                    float x1 = acc[mt][nt][rr * 2];
                    float x2 = acc[mt][nt][rr * 2 + 1];
                    float r1 = x1, r2 = x2;
                    if (MODE >= 2) {
                        const float ang = (float)pos[s] * invf;
                        float sn, cs;
                        sincosf(ang, &sn, &cs);
                        r1 = x1 * cs - x2 * sn;
                        r2 = x1 * sn + x2 * cs;
                    }
                    if (MODE == 3) { r1 *= qscale; r2 *= qscale; }
                    r1 = tf32_rn(r1);
                    r2 = tf32_rn(r2);
                    *(float2*)&out[(((size_t)b * Hc + h) * Sc + s) * HDc + hd] =
                        make_float2(r1, r2);
                }
            }
        }
    }
}

// ---------------------------------------------------------------------------
// Flash attention (causal), tf32 mma.sync, cp.async 2-stage K/V pipeline.
// Unchanged from round 6 (proven).
// ---------------------------------------------------------------------------
constexpr int KSTG      = 16896;              // floats per K/V stage
constexpr int PS_OFF    = 2 * KSTG;           // 33792
constexpr int ATT_SMEMF = PS_OFF + 128 * 64;  // 41984 floats
constexpr int ATT_SMEMB = ATT_SMEMF * 4;      // 167,936 B

__global__ void __launch_bounds__(256, 1)
attn_mma(const float* __restrict__ Q, const float* __restrict__ K,
         const float* __restrict__ V, float* __restrict__ O)
{
    extern __shared__ float smf[];
    const uint32_t smb = smem_u32(smf);

    const int tid  = threadIdx.x;
    const int wid  = tid >> 5;
    const int lane = tid & 31;
    const int g    = lane >> 2;
    const int t4   = lane & 3;
    const int qb   = (gridDim.x - 1) - blockIdx.x;
    const int bh   = blockIdx.y;
    const int q0   = qb * 128;
    const size_t hoff = (size_t)bh * (size_t)(Sc * HDc);
    const int rowb = wid * 16;

    // Stage Q into stage-0 region, swizzled stride 128
    {
        const float* Qg = Q + hoff + (size_t)q0 * HDc;
#pragma unroll
        for (int p = 0; p < 16; p++) {
            int q = tid + p * 256;
            int row = q >> 5;
            int grp = q & 31;
            int sg = (grp & 24) | ((grp & 7) ^ (row & 7));
            CP_ASYNC16(smb + (uint32_t)(row * 128 + sg * 4) * 4u,
                       Qg + (size_t)row * HDc + grp * 4);
        }
        CP_COMMIT();
        CP_WAIT0();
    }
    __syncthreads();

    uint32_t qf[16][4];
#pragma unroll
    for (int ks = 0; ks < 16; ks++) {
        const int g1 = ((2 * ks) & 24) | (((2 * ks) & 7) ^ g);
        const int g2 = ((2 * ks + 1) & 24) | (((2 * ks + 1) & 7) ^ g);
        const int r0 = (rowb + g) * 128;
        const int r1 = (rowb + g + 8) * 128;
        qf[ks][0] = __float_as_uint(smf[r0 + g1 * 4 + t4]);
        qf[ks][1] = __float_as_uint(smf[r1 + g1 * 4 + t4]);
        qf[ks][2] = __float_as_uint(smf[r0 + g2 * 4 + t4]);
        qf[ks][3] = __float_as_uint(smf[r1 + g2 * 4 + t4]);
    }
    __syncthreads();

    const int nkb = 2 * qb + 2;

    auto issue = [&](int kb) {
        const int s = kb & 1;
        const float* Kg = K + hoff + (size_t)(kb * 64) * HDc;
        const float* Vg = V + hoff + (size_t)(kb * 64) * HDc;
        const uint32_t kbase = smb + (uint32_t)(s * KSTG) * 4u;
        const uint32_t vbase = kbase + 8192u * 4u;
#pragma unroll
        for (int p = 0; p < 8; p++) {
            int q = tid + p * 256;
            int row = q >> 5;
            int grp = q & 31;
            int sg = (grp & 24) | ((grp & 7) ^ (row & 7));
            CP_ASYNC16(kbase + (uint32_t)(row * 128 + sg * 4) * 4u,
                       Kg + (size_t)row * HDc + grp * 4);
        }
#pragma unroll
        for (int p = 0; p < 8; p++) {
            int q = tid + p * 256;
            int row = q >> 5;
            int grp = q & 31;
            CP_ASYNC16(vbase + (uint32_t)(row * 136 + grp * 4) * 4u,
                       Vg + (size_t)row * HDc + grp * 4);
        }
    };

    float accO[16][4];
#pragma unroll
    for (int nt = 0; nt < 16; nt++)
#pragma unroll
        for (int r = 0; r < 4; r++) accO[nt][r] = 0.0f;
    float m0 = -1e30f, m1 = -1e30f, l0 = 0.0f, l1 = 0.0f;

    issue(0); CP_COMMIT();
    if (nkb > 1) issue(1);
    CP_COMMIT();

    float* Ps = smf + PS_OFF;

    for (int kb = 0; kb < nkb; kb++) {
        CP_WAIT1();
        __syncthreads();
        const float* Ksb = smf + (kb & 1) * KSTG;
        const float* Vsb = Ksb + 8192;

        float s[8][4];
#pragma unroll
        for (int nt = 0; nt < 8; nt++)
#pragma unroll
            for (int r = 0; r < 4; r++) s[nt][r] = 0.0f;

#pragma unroll
        for (int ks_ = 0; ks_ < 16; ks_++) {
            const int g1 = ((2 * ks_) & 24) | (((2 * ks_) & 7) ^ g);
            const int g2 = ((2 * ks_ + 1) & 24) | (((2 * ks_ + 1) & 7) ^ g);
#pragma unroll
            for (int nt = 0; nt < 8; nt++) {
                uint32_t b[2];
                const int kr = (nt * 8 + g) * 128;
                b[0] = __float_as_uint(Ksb[kr + g1 * 4 + t4]);
                b[1] = __float_as_uint(Ksb[kr + g2 * 4 + t4]);
                mma_tf32(s[nt], qf[ks_], b);
            }
        }

        if (kb >= 2 * qb) {
            const int colb = kb * 64 + 2 * t4;
            const int row0 = q0 + rowb + g;
#pragma unroll
            for (int nt = 0; nt < 8; nt++) {
                const int c0 = colb + nt * 8;
                if (c0     > row0)     s[nt][0] = -1e30f;
                if (c0 + 1 > row0)     s[nt][1] = -1e30f;
                if (c0     > row0 + 8) s[nt][2] = -1e30f;
                if (c0 + 1 > row0 + 8) s[nt][3] = -1e30f;
            }
        }

        float bm0 = -1e30f, bm1 = -1e30f;
#pragma unroll
        for (int nt = 0; nt < 8; nt++) {
            bm0 = fmaxf(bm0, fmaxf(s[nt][0], s[nt][1]));
            bm1 = fmaxf(bm1, fmaxf(s[nt][2], s[nt][3]));
        }
        bm0 = fmaxf(bm0, __shfl_xor_sync(0xffffffffu, bm0, 1));
        bm0 = fmaxf(bm0, __shfl_xor_sync(0xffffffffu, bm0, 2));
        bm1 = fmaxf(bm1, __shfl_xor_sync(0xffffffffu, bm1, 1));
        bm1 = fmaxf(bm1, __shfl_xor_sync(0xffffffffu, bm1, 2));
        const float nm0 = fmaxf(m0, bm0);
        const float nm1 = fmaxf(m1, bm1);
        const float f0 = __expf(m0 - nm0);
        const float f1 = __expf(m1 - nm1);
        float ps0 = 0.0f, ps1 = 0.0f;
        const int prow0 = (rowb + g) * 64;
        const int prow1 = (rowb + g + 8) * 64;
        const int off2  = (2 * t4) & 3;
#pragma unroll
        for (int nt = 0; nt < 8; nt++) {
            float p0 = tf32_rn(__expf(s[nt][0] - nm0));
            float p1 = tf32_rn(__expf(s[nt][1] - nm0));
            float p2 = tf32_rn(__expf(s[nt][2] - nm1));
            float p3 = tf32_rn(__expf(s[nt][3] - nm1));
            ps0 += p0 + p1;
            ps1 += p2 + p3;
            const int f4g = 2 * nt + (t4 >> 1);
            const int sg = (f4g & 8) | ((f4g & 7) ^ g);
            *(float2*)&Ps[prow0 + sg * 4 + off2] = make_float2(p0, p1);
            *(float2*)&Ps[prow1 + sg * 4 + off2] = make_float2(p2, p3);
        }
        ps0 += __shfl_xor_sync(0xffffffffu, ps0, 1);
        ps0 += __shfl_xor_sync(0xffffffffu, ps0, 2);
        ps1 += __shfl_xor_sync(0xffffffffu, ps1, 1);
        ps1 += __shfl_xor_sync(0xffffffffu, ps1, 2);
        l0 = l0 * f0 + ps0;
        l1 = l1 * f1 + ps1;
        m0 = nm0;
        m1 = nm1;
#pragma unroll
        for (int nt = 0; nt < 16; nt++) {
            accO[nt][0] *= f0; accO[nt][1] *= f0;
            accO[nt][2] *= f1; accO[nt][3] *= f1;
        }
        __syncwarp();

#pragma unroll
        for (int ks_ = 0; ks_ < 8; ks_++) {
            uint32_t a[4];
            const int sg1 = ((2 * ks_) & 8) | (((2 * ks_) & 7) ^ g);
            const int sg2 = ((2 * ks_ + 1) & 8) | (((2 * ks_ + 1) & 7) ^ g);
            a[0] = __float_as_uint(Ps[prow0 + sg1 * 4 + t4]);
            a[1] = __float_as_uint(Ps[prow1 + sg1 * 4 + t4]);
            a[2] = __float_as_uint(Ps[prow0 + sg2 * 4 + t4]);
            a[3] = __float_as_uint(Ps[prow1 + sg2 * 4 + t4]);
            const int vr = (8 * ks_ + t4) * 136;
#pragma unroll
            for (int nt = 0; nt < 16; nt++) {
                uint32_t b[2];
                b[0] = __float_as_uint(Vsb[vr + nt * 8 + g]);
                b[1] = __float_as_uint(Vsb[vr + 4 * 136 + nt * 8 + g]);
                mma_tf32(accO[nt], a, b);
            }
        }
        __syncthreads();
        if (kb + 2 < nkb) issue(kb + 2);
        CP_COMMIT();
    }

    const int b_ = bh >> 4;
    const int h_ = bh & 15;
    const float inv0 = 1.0f / l0;
    const float inv1 = 1.0f / l1;
    const int r0g = q0 + rowb + g;
    float* Op0 = O + ((size_t)b_ * Sc + r0g) * Dc + h_ * HDc;
    float* Op1 = Op0 + (size_t)8 * Dc;
#pragma unroll
    for (int nt = 0; nt < 16; nt++) {
        const int cc = nt * 8 + 2 * t4;
        *(float2*)&Op0[cc] = make_float2(accO[nt][0] * inv0, accO[nt][1] * inv0);
        *(float2*)&Op1[cc] = make_float2(accO[nt][2] * inv1, accO[nt][3] * inv1);
    }
}

// ---------------------------------------------------------------------------
extern "C" void kernel_launch(void* const* d_in, const int* in_sizes, int n_in,
                              void* d_out, int out_size)
{
    const float* x  = (const float*)d_in[0];
    const float* wq = (const float*)d_in[1];
    const float* wk = (const float*)d_in[2];
    const float* wv = (const float*)d_in[3];
    const float* wo = (const float*)d_in[4];
    const int* pos  = (const int*)d_in[5];

    float *q, *k, *v, *o;
    cudaGetSymbolAddress((void**)&q, g_Q);
    cudaGetSymbolAddress((void**)&k, g_K);
    cudaGetSymbolAddress((void**)&v, g_V);
    cudaGetSymbolAddress((void**)&o, g_O);

    dim3 gg(Dc / 128, Mc / 128);  // (16, 64)
    gemm_fp16<3><<<gg, 256>>>(x, wq, q, pos);   // Q proj + RoPE + scale + round
    gemm_fp16<2><<<gg, 256>>>(x, wk, k, pos);   // K proj + RoPE + round
    gemm_fp16<1><<<gg, 256>>>(x, wv, v, pos);   // V proj + round

    cudaFuncSetAttribute(attn_mma,
                         cudaFuncAttributeMaxDynamicSharedMemorySize, ATT_SMEMB);
    attn_mma<<<dim3(Sc / 128, Bc * Hc), 256, ATT_SMEMB>>>(q, k, v, o);

    gemm_fp16<0><<<gg, 256>>>(o, wo, (float*)d_out, pos);  // output proj
}

// round 9
// speedup vs baseline: 1.6673x; 1.1361x over previous
#include <cuda_runtime.h>
#include <cuda_fp16.h>
#include <math.h>
#include <stdint.h>

// Problem dims
constexpr int Bc = 4, Sc = 2048, Dc = 2048, Hc = 16, HDc = 128;
constexpr int Mc = Bc * Sc;

// Scratch
__device__ __half g_Qh[Bc * Hc * Sc * HDc];  // [B,H,S,HD] fp16, pre-scaled 1/sqrt(HD)
__device__ __half g_Kh[Bc * Hc * Sc * HDc];  // [B,H,S,HD] fp16
__device__ __half g_Vh[Bc * Hc * Sc * HDc];  // [B,H,HD,S] fp16 (TRANSPOSED per head)
__device__ float  g_O [Bc * Sc * Dc];        // [B,S,D]

// ---------------------------------------------------------------------------
// helpers (sm_103 base target: mma.sync + cp.async only)
// ---------------------------------------------------------------------------
__device__ __forceinline__ void mma_fp16(float* d, const uint32_t* a, const uint32_t* b) {
    asm volatile(
        "mma.sync.aligned.m16n8k16.row.col.f32.f16.f16.f32 "
        "{%0,%1,%2,%3},{%4,%5,%6,%7},{%8,%9},{%0,%1,%2,%3};"
        : "+f"(d[0]), "+f"(d[1]), "+f"(d[2]), "+f"(d[3])
        : "r"(a[0]), "r"(a[1]), "r"(a[2]), "r"(a[3]), "r"(b[0]), "r"(b[1]));
}

__device__ __forceinline__ uint32_t h2u(float x, float y) {
    __half2 h = __float22half2_rn(make_float2(x, y));
    return *(uint32_t*)&h;
}

__device__ __forceinline__ uint32_t smem_u32(const void* p) {
    uint32_t a;
    asm("{ .reg .u64 t; cvta.to.shared.u64 t, %1; cvt.u32.u64 %0, t; }"
        : "=r"(a) : "l"(p));
    return a;
}

#define CP_ASYNC16(dst, src) \
    asm volatile("cp.async.cg.shared.global [%0], [%1], 16;" :: "r"(dst), "l"(src))
#define CP_COMMIT() asm volatile("cp.async.commit_group;" ::: "memory")
#define CP_WAIT1()  asm volatile("cp.async.wait_group 1;" ::: "memory")
#define CP_WAIT0()  asm volatile("cp.async.wait_group 0;" ::: "memory")

// ---------------------------------------------------------------------------
// GEMM via fp16 mma.sync m16n8k16 (fp32 accumulate), proven round-7 form.
// C[M,N] = A[M,K]*W[N,K]^T. CTA 128x128x32, 8 warps, warp 64x32.
// MODE 0: plain fp32 [M,N]                              (out proj)
// MODE 1: fp16, scatter TRANSPOSED [B,H,HD,S]           (V)
// MODE 2: fp16, scatter [B,H,S,HD] + RoPE               (K)
// MODE 3: fp16, scatter [B,H,S,HD] + RoPE + 1/sqrt(HD)  (Q)
// ---------------------------------------------------------------------------
template <int MODE>
__global__ void __launch_bounds__(256, 2)
gemm_fp16(const float* __restrict__ A, const float* __restrict__ W,
          void* __restrict__ outv, const int* __restrict__ pos)
{
    constexpr int Kd = Dc;
    constexpr int Nd = Dc;
    constexpr int LDS = 20;                 // u32 (half2) per row
    __shared__ uint32_t AsU[128 * LDS];
    __shared__ uint32_t BsU[128 * LDS];

    const int tid  = threadIdx.x;
    const int bm   = blockIdx.y * 128;
    const int bn   = blockIdx.x * 128;
    const int wid  = tid >> 5;
    const int lane = tid & 31;
    const int wm   = (wid >> 2) * 64;
    const int wn   = (wid & 3) * 32;
    const int g    = lane >> 2;
    const int t4   = lane & 3;

    const int lr  = tid >> 3;
    const int lc4 = tid & 7;
    const float* Ag = A + (size_t)(bm + lr) * Kd + lc4 * 4;
    const float* Wg = W + (size_t)(bn + lr) * Kd + lc4 * 4;

    float acc[4][4][4];
#pragma unroll
    for (int mt = 0; mt < 4; mt++)
#pragma unroll
        for (int nt = 0; nt < 4; nt++)
#pragma unroll
            for (int r = 0; r < 4; r++) acc[mt][nt][r] = 0.0f;

    float4 pa[4], pb[4];
#pragma unroll
    for (int p = 0; p < 4; p++) {
        pa[p] = *(const float4*)(Ag + (size_t)p * 32 * Kd);
        pb[p] = *(const float4*)(Wg + (size_t)p * 32 * Kd);
    }

    for (int kt = 0; kt < Kd; kt += 32) {
#pragma unroll
        for (int p = 0; p < 4; p++) {
            const int ro = (lr + p * 32) * LDS + 2 * lc4;
            AsU[ro]     = h2u(pa[p].x, pa[p].y);
            AsU[ro + 1] = h2u(pa[p].z, pa[p].w);
            BsU[ro]     = h2u(pb[p].x, pb[p].y);
            BsU[ro + 1] = h2u(pb[p].z, pb[p].w);
        }
        __syncthreads();

        if (kt + 32 < Kd) {
#pragma unroll
            for (int p = 0; p < 4; p++) {
                pa[p] = *(const float4*)(Ag + (size_t)p * 32 * Kd + kt + 32);
                pb[p] = *(const float4*)(Wg + (size_t)p * 32 * Kd + kt + 32);
            }
        }

#pragma unroll
        for (int ks = 0; ks < 2; ks++) {
            const int k0 = ks * 8;
            uint32_t af[4][4], bf[4][2];
#pragma unroll
            for (int mt = 0; mt < 4; mt++) {
                const int r0 = (wm + mt * 16 + g) * LDS + k0 + t4;
                af[mt][0] = AsU[r0];
                af[mt][1] = AsU[r0 + 8 * LDS];
                af[mt][2] = AsU[r0 + 4];
                af[mt][3] = AsU[r0 + 8 * LDS + 4];
            }
#pragma unroll
            for (int nt = 0; nt < 4; nt++) {
                const int c0 = (wn + nt * 8 + g) * LDS + k0 + t4;
                bf[nt][0] = BsU[c0];
                bf[nt][1] = BsU[c0 + 4];
            }
#pragma unroll
            for (int mt = 0; mt < 4; mt++)
#pragma unroll
                for (int nt = 0; nt < 4; nt++)
                    mma_fp16(acc[mt][nt], af[mt], bf[nt]);
        }
        __syncthreads();
    }

    const float qscale = 0.08838834764831845f;  // 1/sqrt(128)
#pragma unroll
    for (int nt = 0; nt < 4; nt++) {
        const int col = bn + wn + nt * 8 + 2 * t4;
        if (MODE == 0) {
            float* out = (float*)outv;
#pragma unroll
            for (int mt = 0; mt < 4; mt++) {
                const int r0 = bm + wm + mt * 16 + g;
                *(float2*)&out[(size_t)r0 * Nd + col] =
                    make_float2(acc[mt][nt][0], acc[mt][nt][1]);
                *(float2*)&out[(size_t)(r0 + 8) * Nd + col] =
                    make_float2(acc[mt][nt][2], acc[mt][nt][3]);
            }
        } else {
            __half* oh = (__half*)outv;
            const int h  = col >> 7;
            const int hd = col & 127;
            float invf = 0.0f;
            if (MODE >= 2)
                invf = (float)exp2(-(double)hd * (13.287712379549449 / 128.0));
#pragma unroll
            for (int mt = 0; mt < 4; mt++) {
#pragma unroll
                for (int rr = 0; rr < 2; rr++) {
                    const int m = bm + wm + mt * 16 + g + rr * 8;
                    const int b = m >> 11;
                    const int s = m & 2047;
                    float x1 = acc[mt][nt][rr * 2];
                    float x2 = acc[mt][nt][rr * 2 + 1];
                    float r1 = x1, r2 = x2;
                    if (MODE >= 2) {
                        const float ang = (float)pos[s] * invf;
                        float sn, cs;
                        sincosf(ang, &sn, &cs);
                        r1 = x1 * cs - x2 * sn;
                        r2 = x1 * sn + x2 * cs;
                    }
                    if (MODE == 3) { r1 *= qscale; r2 *= qscale; }
                    if (MODE == 1) {
                        // V transposed: [B,H,HD,S]
                        const size_t base = ((size_t)b * Hc + h) * HDc;
                        oh[(base + hd)     * Sc + s] = __float2half_rn(r1);
                        oh[(base + hd + 1) * Sc + s] = __float2half_rn(r2);
                    } else {
                        *(uint32_t*)&oh[(((size_t)b * Hc + h) * Sc + s) * HDc + hd] =
                            h2u(r1, r2);
                    }
                }
            }
        }
    }
}

// ---------------------------------------------------------------------------
// Flash attention (causal), fp16 mma.sync m16n8k16, cp.async 2-stage K/V.
// Q,K in [B,H,S,HD] fp16 (Q pre-scaled); V in [B,H,HD,S] fp16 (transposed).
// CTA: 128 q-rows x one (b,h); 8 warps x 16 rows; key tiles of 64.
// Row of Q/K = 128 halves = 64 u32 = 16 chunks of 16B (stride 68 u32).
// Row of VsT/Ps = 64 keys = 32 u32 = 8 chunks (stride 36 u32).
// smem (u32): stage s at s*8960: K 64x68 (4352) + VsT 128x36 (4608);
//             Ps 128x36 at 17920. Total 22528 u32 = 90112 B.
// ---------------------------------------------------------------------------
constexpr int KSTG_U    = 8960;
constexpr int VOFF_U    = 4352;
constexpr int PS_U      = 17920;
constexpr int ATT_SMEMB = (PS_U + 128 * 36) * 4;   // 90112 B

__global__ void __launch_bounds__(256, 1)
attn_mma(const __half* __restrict__ Q, const __half* __restrict__ K,
         const __half* __restrict__ V, float* __restrict__ O)
{
    extern __shared__ uint32_t smu[];
    const uint32_t smb = smem_u32(smu);

    const int tid  = threadIdx.x;
    const int wid  = tid >> 5;
    const int lane = tid & 31;
    const int g    = lane >> 2;
    const int t4   = lane & 3;
    const int qb   = (gridDim.x - 1) - blockIdx.x;   // heavy blocks first
    const int bh   = blockIdx.y;
    const int q0   = qb * 128;
    const size_t hoff = (size_t)bh * (size_t)(Sc * HDc);
    const int rowb = wid * 16;

    // ---- Stage Q: 128 rows x 16 chunks = 2048 chunks, stride 68 u32
    {
        const __half* Qg = Q + hoff + (size_t)q0 * HDc;
#pragma unroll
        for (int p = 0; p < 8; p++) {
            int q = tid + p * 256;          // 0..2047
            int row = q >> 4;               // 0..127
            int c4 = q & 15;                // 0..15 (16B chunks)
            CP_ASYNC16(smb + (uint32_t)(row * 68 + c4 * 4) * 4u,
                       Qg + (size_t)row * HDc + c4 * 8);
        }
        CP_COMMIT();
        CP_WAIT0();
    }
    __syncthreads();

    // ---- Extract Q fragments (m16n8k16 A): qf[ks][0..3]
    uint32_t qf[8][4];
#pragma unroll
    for (int ks = 0; ks < 8; ks++) {
        const int r0 = (rowb + g) * 68 + 8 * ks + t4;
        const int r1 = r0 + 8 * 68;
        qf[ks][0] = smu[r0];
        qf[ks][1] = smu[r1];
        qf[ks][2] = smu[r0 + 4];
        qf[ks][3] = smu[r1 + 4];
    }
    __syncthreads();

    const int nkb = 2 * qb + 2;

    auto issue = [&](int kb) {
        const int s = kb & 1;
        const __half* Kg = K + hoff + (size_t)(kb * 64) * HDc;
        const __half* Vg = V + hoff + (size_t)kb * 64;   // [HD][S] per head
        const uint32_t kbase = smb + (uint32_t)(s * KSTG_U) * 4u;
        const uint32_t vbase = kbase + (uint32_t)VOFF_U * 4u;
        // K: 64 rows x 16 chunks = 1024
#pragma unroll
        for (int p = 0; p < 4; p++) {
            int q = tid + p * 256;
            int row = q >> 4;               // 0..63
            int c4 = q & 15;
            CP_ASYNC16(kbase + (uint32_t)(row * 68 + c4 * 4) * 4u,
                       Kg + (size_t)row * HDc + c4 * 8);
        }
        // VsT: 128 rows (hd) x 8 chunks = 1024
#pragma unroll
        for (int p = 0; p < 4; p++) {
            int q = tid + p * 256;
            int row = q >> 3;               // 0..127
            int c4 = q & 7;                 // 0..7
            CP_ASYNC16(vbase + (uint32_t)(row * 36 + c4 * 4) * 4u,
                       Vg + (size_t)row * Sc + c4 * 8);
        }
    };

    float accO[16][4];
#pragma unroll
    for (int nt = 0; nt < 16; nt++)
#pragma unroll
        for (int r = 0; r < 4; r++) accO[nt][r] = 0.0f;
    float m0 = -1e30f, m1 = -1e30f, l0 = 0.0f, l1 = 0.0f;

    issue(0); CP_COMMIT();
    if (nkb > 1) issue(1);
    CP_COMMIT();

    uint32_t* Psu = smu + PS_U;

    for (int kb = 0; kb < nkb; kb++) {
        CP_WAIT1();
        __syncthreads();
        const uint32_t* Ku = smu + (kb & 1) * KSTG_U;
        const uint32_t* Vu = Ku + VOFF_U;

        // ---- Scores: warp rows [rowb, rowb+16) x 64 keys (8 n-tiles)
        float s[8][4];
#pragma unroll
        for (int nt = 0; nt < 8; nt++)
#pragma unroll
            for (int r = 0; r < 4; r++) s[nt][r] = 0.0f;

#pragma unroll
        for (int ks_ = 0; ks_ < 8; ks_++) {
#pragma unroll
            for (int nt = 0; nt < 8; nt++) {
                uint32_t b[2];
                const int kr = (nt * 8 + g) * 68 + 8 * ks_ + t4;
                b[0] = Ku[kr];
                b[1] = Ku[kr + 4];
                mma_fp16(s[nt], qf[ks_], b);
            }
        }

        // ---- Causal mask (diagonal tiles only)
        if (kb >= 2 * qb) {
            const int colb = kb * 64 + 2 * t4;
            const int row0 = q0 + rowb + g;
#pragma unroll
            for (int nt = 0; nt < 8; nt++) {
                const int c0 = colb + nt * 8;
                if (c0     > row0)     s[nt][0] = -1e30f;
                if (c0 + 1 > row0)     s[nt][1] = -1e30f;
                if (c0     > row0 + 8) s[nt][2] = -1e30f;
                if (c0 + 1 > row0 + 8) s[nt][3] = -1e30f;
            }
        }

        // ---- Online softmax (rows g, g+8)
        float bm0 = -1e30f, bm1 = -1e30f;
#pragma unroll
        for (int nt = 0; nt < 8; nt++) {
            bm0 = fmaxf(bm0, fmaxf(s[nt][0], s[nt][1]));
            bm1 = fmaxf(bm1, fmaxf(s[nt][2], s[nt][3]));
        }
        bm0 = fmaxf(bm0, __shfl_xor_sync(0xffffffffu, bm0, 1));
        bm0 = fmaxf(bm0, __shfl_xor_sync(0xffffffffu, bm0, 2));
        bm1 = fmaxf(bm1, __shfl_xor_sync(0xffffffffu, bm1, 1));
        bm1 = fmaxf(bm1, __shfl_xor_sync(0xffffffffu, bm1, 2));
        const float nm0 = fmaxf(m0, bm0);
        const float nm1 = fmaxf(m1, bm1);
        const float f0 = __expf(m0 - nm0);
        const float f1 = __expf(m1 - nm1);
        float ps0 = 0.0f, ps1 = 0.0f;
        const int pr0 = (rowb + g) * 36;
        const int pr1 = pr0 + 8 * 36;
#pragma unroll
        for (int nt = 0; nt < 8; nt++) {
            float p0 = __expf(s[nt][0] - nm0);
            float p1 = __expf(s[nt][1] - nm0);
            float p2 = __expf(s[nt][2] - nm1);
            float p3 = __expf(s[nt][3] - nm1);
            ps0 += p0 + p1;
            ps1 += p2 + p3;
            Psu[pr0 + nt * 4 + t4] = h2u(p0, p1);
            Psu[pr1 + nt * 4 + t4] = h2u(p2, p3);
        }
        ps0 += __shfl_xor_sync(0xffffffffu, ps0, 1);
        ps0 += __shfl_xor_sync(0xffffffffu, ps0, 2);
        ps1 += __shfl_xor_sync(0xffffffffu, ps1, 1);
        ps1 += __shfl_xor_sync(0xffffffffu, ps1, 2);
        l0 = l0 * f0 + ps0;
        l1 = l1 * f1 + ps1;
        m0 = nm0;
        m1 = nm1;
#pragma unroll
        for (int nt = 0; nt < 16; nt++) {
            accO[nt][0] *= f0; accO[nt][1] *= f0;
            accO[nt][2] *= f1; accO[nt][3] *= f1;
        }
        __syncwarp();  // Ps rows are warp-private

        // ---- PV: accO += P[16x64] * V[64x128] (4 k16 steps, 16 n-tiles)
#pragma unroll
        for (int ks_ = 0; ks_ < 4; ks_++) {
            uint32_t a[4];
            const int a0 = pr0 + 8 * ks_ + t4;
            const int a1 = pr1 + 8 * ks_ + t4;
            a[0] = Psu[a0];
            a[1] = Psu[a1];
            a[2] = Psu[a0 + 4];
            a[3] = Psu[a1 + 4];
#pragma unroll
            for (int nt = 0; nt < 16; nt++) {
                uint32_t b[2];
                const int vr = (nt * 8 + g) * 36 + 8 * ks_ + t4;
                b[0] = Vu[vr];
                b[1] = Vu[vr + 4];
                mma_fp16(accO[nt], a, b);
            }
        }
        __syncthreads();   // all warps done with stage (kb&1)
        if (kb + 2 < nkb) issue(kb + 2);
        CP_COMMIT();
    }

    // ---- Normalize + write O in [B,S,D]
    const int b_ = bh >> 4;
    const int h_ = bh & 15;
    const float inv0 = 1.0f / l0;
    const float inv1 = 1.0f / l1;
    const int r0g = q0 + rowb + g;
    float* Op0 = O + ((size_t)b_ * Sc + r0g) * Dc + h_ * HDc;
    float* Op1 = Op0 + (size_t)8 * Dc;
#pragma unroll
    for (int nt = 0; nt < 16; nt++) {
        const int cc = nt * 8 + 2 * t4;
        *(float2*)&Op0[cc] = make_float2(accO[nt][0] * inv0, accO[nt][1] * inv0);
        *(float2*)&Op1[cc] = make_float2(accO[nt][2] * inv1, accO[nt][3] * inv1);
    }
}

// ---------------------------------------------------------------------------
extern "C" void kernel_launch(void* const* d_in, const int* in_sizes, int n_in,
                              void* d_out, int out_size)
{
    const float* x  = (const float*)d_in[0];
    const float* wq = (const float*)d_in[1];
    const float* wk = (const float*)d_in[2];
    const float* wv = (const float*)d_in[3];
    const float* wo = (const float*)d_in[4];
    const int* pos  = (const int*)d_in[5];

    __half *q, *k, *v;
    float *o;
    cudaGetSymbolAddress((void**)&q, g_Qh);
    cudaGetSymbolAddress((void**)&k, g_Kh);
    cudaGetSymbolAddress((void**)&v, g_Vh);
    cudaGetSymbolAddress((void**)&o, g_O);

    dim3 gg(Dc / 128, Mc / 128);  // (16, 64)
    gemm_fp16<3><<<gg, 256>>>(x, wq, q, pos);   // Q proj + RoPE + scale -> fp16
    gemm_fp16<2><<<gg, 256>>>(x, wk, k, pos);   // K proj + RoPE -> fp16
    gemm_fp16<1><<<gg, 256>>>(x, wv, v, pos);   // V proj -> fp16 transposed

    cudaFuncSetAttribute(attn_mma,
                         cudaFuncAttributeMaxDynamicSharedMemorySize, ATT_SMEMB);
    attn_mma<<<dim3(Sc / 128, Bc * Hc), 256, ATT_SMEMB>>>(q, k, v, o);

    gemm_fp16<0><<<gg, 256>>>(o, wo, d_out, pos);  // output proj (fp32 out)
}

// round 10
// speedup vs baseline: 2.0843x; 1.2501x over previous
#include <cuda_runtime.h>
#include <cuda_fp16.h>
#include <math.h>
#include <stdint.h>

// Problem dims
constexpr int Bc = 4, Sc = 2048, Dc = 2048, Hc = 16, HDc = 128;
constexpr int Mc = Bc * Sc;

// Scratch (fp16 everywhere between stages)
__device__ __half g_xh [Mc * Dc];            // x converted to fp16
__device__ __half g_wqh[Dc * Dc];
__device__ __half g_wkh[Dc * Dc];
__device__ __half g_wvh[Dc * Dc];
__device__ __half g_woh[Dc * Dc];
__device__ __half g_Qh [Bc * Hc * Sc * HDc]; // [B,H,S,HD], pre-scaled 1/sqrt(HD)
__device__ __half g_Kh [Bc * Hc * Sc * HDc]; // [B,H,S,HD]
__device__ __half g_Vh [Bc * Hc * Sc * HDc]; // [B,H,HD,S] (TRANSPOSED per head)
__device__ __half g_Oh [Mc * Dc];            // attention output [B,S,D] fp16

// ---------------------------------------------------------------------------
// helpers (sm_103 base target: mma.sync + cp.async + ldmatrix only)
// ---------------------------------------------------------------------------
__device__ __forceinline__ void mma_fp16(float* d, const uint32_t* a, const uint32_t* b) {
    asm volatile(
        "mma.sync.aligned.m16n8k16.row.col.f32.f16.f16.f32 "
        "{%0,%1,%2,%3},{%4,%5,%6,%7},{%8,%9},{%0,%1,%2,%3};"
        : "+f"(d[0]), "+f"(d[1]), "+f"(d[2]), "+f"(d[3])
        : "r"(a[0]), "r"(a[1]), "r"(a[2]), "r"(a[3]), "r"(b[0]), "r"(b[1]));
}

__device__ __forceinline__ void ldsm_x4(uint32_t* r, uint32_t addr) {
    asm volatile("ldmatrix.sync.aligned.m8n8.x4.shared.b16 {%0,%1,%2,%3}, [%4];"
        : "=r"(r[0]), "=r"(r[1]), "=r"(r[2]), "=r"(r[3]) : "r"(addr));
}

__device__ __forceinline__ uint32_t h2u(float x, float y) {
    __half2 h = __float22half2_rn(make_float2(x, y));
    return *(uint32_t*)&h;
}

__device__ __forceinline__ uint32_t smem_u32(const void* p) {
    uint32_t a;
    asm("{ .reg .u64 t; cvta.to.shared.u64 t, %1; cvt.u32.u64 %0, t; }"
        : "=r"(a) : "l"(p));
    return a;
}

#define CP_ASYNC16(dst, src) \
    asm volatile("cp.async.cg.shared.global [%0], [%1], 16;" :: "r"(dst), "l"(src))
#define CP_COMMIT() asm volatile("cp.async.commit_group;" ::: "memory")
#define CP_WAIT1()  asm volatile("cp.async.wait_group 1;" ::: "memory")
#define CP_WAIT0()  asm volatile("cp.async.wait_group 0;" ::: "memory")

// ---------------------------------------------------------------------------
// fp32 -> fp16 conversion (elementwise, float4 vectorized)
// ---------------------------------------------------------------------------
__global__ void f2h_kernel(const float* __restrict__ in, __half* __restrict__ out, int n4)
{
    int i = blockIdx.x * blockDim.x + threadIdx.x;
    if (i < n4) {
        float4 v = ((const float4*)in)[i];
        uint2 o;
        o.x = h2u(v.x, v.y);
        o.y = h2u(v.z, v.w);
        ((uint2*)out)[i] = o;
    }
}

// ---------------------------------------------------------------------------
// GEMM: C[M,N] = A[M,K]*W[N,K]^T, fp16 inputs, fp16 mma m16n8k16, fp32 accum.
// CTA 128x128x32, 8 warps, warp 64x32; cp.async 3-stage ring; ldmatrix frags.
// smem: stage s at s*5120 u32: A 128x20, B 128x20 (stride 20 u32: ldmatrix
// row-address banks {0,20,8,28,16,4,24,12} -> conflict-free).
// MODE 0: plain fp32 [M,N]                              (out proj)
// MODE 1: fp16, scatter TRANSPOSED [B,H,HD,S]           (V)
// MODE 2: fp16, scatter [B,H,S,HD] + RoPE               (K)
// MODE 3: fp16, scatter [B,H,S,HD] + RoPE + 1/sqrt(HD)  (Q)
// ---------------------------------------------------------------------------
constexpr int LDSg   = 20;                    // u32 per row
constexpr int STG_U  = 2 * 128 * LDSg;        // 5120 u32 per stage
constexpr int GSMEMB = 3 * STG_U * 4;         // 61440 B

template <int MODE>
__global__ void __launch_bounds__(256, 2)
gemm_fp16h(const __half* __restrict__ A, const __half* __restrict__ W,
           void* __restrict__ outv, const int* __restrict__ pos)
{
    extern __shared__ uint32_t smu[];
    constexpr int Kd = Dc;
    constexpr int Nd = Dc;
    const uint32_t smb = smem_u32(smu);

    const int tid  = threadIdx.x;
    const int bm   = blockIdx.y * 128;
    const int bn   = blockIdx.x * 128;
    const int wid  = tid >> 5;
    const int lane = tid & 31;
    const int wm   = (wid >> 2) * 64;
    const int wn   = (wid & 3) * 32;
    const int g    = lane >> 2;
    const int t4   = lane & 3;

    // loader: rows lrow, lrow+64; 16B chunk lc4 within 32-half k-tile
    const int lrow = tid >> 2;               // 0..63
    const int lc4  = tid & 3;                // 0..3
    const __half* Ag = A + (size_t)(bm + lrow) * Kd + lc4 * 8;
    const __half* Wg = W + (size_t)(bn + lrow) * Kd + lc4 * 8;
    const uint32_t dstA = (uint32_t)(lrow * LDSg + lc4 * 4);

    auto issue_stage = [&](int s, int kt) {
        const uint32_t so = (uint32_t)(s * STG_U);
        const int ko = kt * 32;
        CP_ASYNC16(smb + (so + dstA) * 4u,                    Ag + ko);
        CP_ASYNC16(smb + (so + dstA + 64 * LDSg) * 4u,        Ag + (size_t)64 * Kd + ko);
        CP_ASYNC16(smb + (so + 2560 + dstA) * 4u,             Wg + ko);
        CP_ASYNC16(smb + (so + 2560 + dstA + 64 * LDSg) * 4u, Wg + (size_t)64 * Kd + ko);
    };

    // ldmatrix per-thread byte offsets (within a stage's A / B region)
    const uint32_t aoff = (uint32_t)((wm + (lane & 7) + ((lane >> 3) & 1) * 8) * LDSg
                                     + ((lane >> 4) & 1) * 4) * 4u;
    const uint32_t boff = (uint32_t)((wn + (lane & 7) + (lane >> 4) * 8) * LDSg
                                     + ((lane >> 3) & 1) * 4) * 4u;

    float acc[4][4][4];
#pragma unroll
    for (int mt = 0; mt < 4; mt++)
#pragma unroll
        for (int nt = 0; nt < 4; nt++)
#pragma unroll
            for (int r = 0; r < 4; r++) acc[mt][nt][r] = 0.0f;

    issue_stage(0, 0); CP_COMMIT();
    issue_stage(1, 1); CP_COMMIT();

    constexpr int NKT = Kd / 32;  // 64
    for (int kt = 0; kt < NKT; kt++) {
        const int s = kt % 3;
        CP_WAIT1();
        __syncthreads();
        if (kt + 2 < NKT) issue_stage((kt + 2) % 3, kt + 2);
        CP_COMMIT();

        const uint32_t abase = smb + (uint32_t)(s * STG_U) * 4u + aoff;
        const uint32_t bbase = smb + (uint32_t)(s * STG_U + 2560) * 4u + boff;
#pragma unroll
        for (int ks = 0; ks < 2; ks++) {
            const uint32_t ko = (uint32_t)(ks * 32);
            uint32_t af[4][4], bf0[4], bf1[4];
            ldsm_x4(af[0], abase + ko);
            ldsm_x4(af[1], abase + ko + 1280u);
            ldsm_x4(af[2], abase + ko + 2560u);
            ldsm_x4(af[3], abase + ko + 3840u);
            ldsm_x4(bf0, bbase + ko);            // n-tiles 0,1
            ldsm_x4(bf1, bbase + ko + 1280u);    // n-tiles 2,3
#pragma unroll
            for (int mt = 0; mt < 4; mt++) {
                mma_fp16(acc[mt][0], af[mt], bf0);
                mma_fp16(acc[mt][1], af[mt], bf0 + 2);
                mma_fp16(acc[mt][2], af[mt], bf1);
                mma_fp16(acc[mt][3], af[mt], bf1 + 2);
            }
        }
    }

    const float qscale = 0.08838834764831845f;  // 1/sqrt(128)
#pragma unroll
    for (int nt = 0; nt < 4; nt++) {
        const int col = bn + wn + nt * 8 + 2 * t4;
        if (MODE == 0) {
            float* out = (float*)outv;
#pragma unroll
            for (int mt = 0; mt < 4; mt++) {
                const int r0 = bm + wm + mt * 16 + g;
                *(float2*)&out[(size_t)r0 * Nd + col] =
                    make_float2(acc[mt][nt][0], acc[mt][nt][1]);
                *(float2*)&out[(size_t)(r0 + 8) * Nd + col] =
                    make_float2(acc[mt][nt][2], acc[mt][nt][3]);
            }
        } else {
            __half* oh = (__half*)outv;
            const int h  = col >> 7;
            const int hd = col & 127;
            float invf = 0.0f;
            if (MODE >= 2)
                invf = (float)exp2(-(double)hd * (13.287712379549449 / 128.0));
#pragma unroll
            for (int mt = 0; mt < 4; mt++) {
#pragma unroll
                for (int rr = 0; rr < 2; rr++) {
                    const int m = bm + wm + mt * 16 + g + rr * 8;
                    const int b = m >> 11;
                    const int s = m & 2047;
                    float x1 = acc[mt][nt][rr * 2];
                    float x2 = acc[mt][nt][rr * 2 + 1];
                    float r1 = x1, r2 = x2;
                    if (MODE >= 2) {
                        const float ang = (float)pos[s] * invf;
                        float sn, cs;
                        sincosf(ang, &sn, &cs);
                        r1 = x1 * cs - x2 * sn;
                        r2 = x1 * sn + x2 * cs;
                    }
                    if (MODE == 3) { r1 *= qscale; r2 *= qscale; }
                    if (MODE == 1) {
                        // V transposed: [B,H,HD,S]
                        const size_t base = ((size_t)b * Hc + h) * HDc;
                        oh[(base + hd)     * Sc + s] = __float2half_rn(r1);
                        oh[(base + hd + 1) * Sc + s] = __float2half_rn(r2);
                    } else {
                        *(uint32_t*)&oh[(((size_t)b * Hc + h) * Sc + s) * HDc + hd] =
                            h2u(r1, r2);
                    }
                }
            }
        }
    }
}

// ---------------------------------------------------------------------------
// Flash attention (causal), fp16 mma m16n8k16, cp.async 2-stage K/V.
// Round-9 proven form; only change: O written as fp16 [B,S,D].
// ---------------------------------------------------------------------------
constexpr int KSTG_U    = 8960;
constexpr int VOFF_U    = 4352;
constexpr int PS_U      = 17920;
constexpr int ATT_SMEMB = (PS_U + 128 * 36) * 4;   // 90112 B

__global__ void __launch_bounds__(256, 1)
attn_mma(const __half* __restrict__ Q, const __half* __restrict__ K,
         const __half* __restrict__ V, __half* __restrict__ O)
{
    extern __shared__ uint32_t smu[];
    const uint32_t smb = smem_u32(smu);

    const int tid  = threadIdx.x;
    const int wid  = tid >> 5;
    const int lane = tid & 31;
    const int g    = lane >> 2;
    const int t4   = lane & 3;
    const int qb   = (gridDim.x - 1) - blockIdx.x;   // heavy blocks first
    const int bh   = blockIdx.y;
    const int q0   = qb * 128;
    const size_t hoff = (size_t)bh * (size_t)(Sc * HDc);
    const int rowb = wid * 16;

    // ---- Stage Q: 128 rows x 16 chunks, stride 68 u32
    {
        const __half* Qg = Q + hoff + (size_t)q0 * HDc;
#pragma unroll
        for (int p = 0; p < 8; p++) {
            int q = tid + p * 256;
            int row = q >> 4;
            int c4 = q & 15;
            CP_ASYNC16(smb + (uint32_t)(row * 68 + c4 * 4) * 4u,
                       Qg + (size_t)row * HDc + c4 * 8);
        }
        CP_COMMIT();
        CP_WAIT0();
    }
    __syncthreads();

    uint32_t qf[8][4];
#pragma unroll
    for (int ks = 0; ks < 8; ks++) {
        const int r0 = (rowb + g) * 68 + 8 * ks + t4;
        const int r1 = r0 + 8 * 68;
        qf[ks][0] = smu[r0];
        qf[ks][1] = smu[r1];
        qf[ks][2] = smu[r0 + 4];
        qf[ks][3] = smu[r1 + 4];
    }
    __syncthreads();

    const int nkb = 2 * qb + 2;

    auto issue = [&](int kb) {
        const int s = kb & 1;
        const __half* Kg = K + hoff + (size_t)(kb * 64) * HDc;
        const __half* Vg = V + hoff + (size_t)kb * 64;   // [HD][S] per head
        const uint32_t kbase = smb + (uint32_t)(s * KSTG_U) * 4u;
        const uint32_t vbase = kbase + (uint32_t)VOFF_U * 4u;
#pragma unroll
        for (int p = 0; p < 4; p++) {
            int q = tid + p * 256;
            int row = q >> 4;
            int c4 = q & 15;
            CP_ASYNC16(kbase + (uint32_t)(row * 68 + c4 * 4) * 4u,
                       Kg + (size_t)row * HDc + c4 * 8);
        }
#pragma unroll
        for (int p = 0; p < 4; p++) {
            int q = tid + p * 256;
            int row = q >> 3;
            int c4 = q & 7;
            CP_ASYNC16(vbase + (uint32_t)(row * 36 + c4 * 4) * 4u,
                       Vg + (size_t)row * Sc + c4 * 8);
        }
    };

    float accO[16][4];
#pragma unroll
    for (int nt = 0; nt < 16; nt++)
#pragma unroll
        for (int r = 0; r < 4; r++) accO[nt][r] = 0.0f;
    float m0 = -1e30f, m1 = -1e30f, l0 = 0.0f, l1 = 0.0f;

    issue(0); CP_COMMIT();
    if (nkb > 1) issue(1);
    CP_COMMIT();

    uint32_t* Psu = smu + PS_U;

    for (int kb = 0; kb < nkb; kb++) {
        CP_WAIT1();
        __syncthreads();
        const uint32_t* Ku = smu + (kb & 1) * KSTG_U;
        const uint32_t* Vu = Ku + VOFF_U;

        float s[8][4];
#pragma unroll
        for (int nt = 0; nt < 8; nt++)
#pragma unroll
            for (int r = 0; r < 4; r++) s[nt][r] = 0.0f;

#pragma unroll
        for (int ks_ = 0; ks_ < 8; ks_++) {
#pragma unroll
            for (int nt = 0; nt < 8; nt++) {
                uint32_t b[2];
                const int kr = (nt * 8 + g) * 68 + 8 * ks_ + t4;
                b[0] = Ku[kr];
                b[1] = Ku[kr + 4];
                mma_fp16(s[nt], qf[ks_], b);
            }
        }

        if (kb >= 2 * qb) {
            const int colb = kb * 64 + 2 * t4;
            const int row0 = q0 + rowb + g;
#pragma unroll
            for (int nt = 0; nt < 8; nt++) {
                const int c0 = colb + nt * 8;
                if (c0     > row0)     s[nt][0] = -1e30f;
                if (c0 + 1 > row0)     s[nt][1] = -1e30f;
                if (c0     > row0 + 8) s[nt][2] = -1e30f;
                if (c0 + 1 > row0 + 8) s[nt][3] = -1e30f;
            }
        }

        float bm0 = -1e30f, bm1 = -1e30f;
#pragma unroll
        for (int nt = 0; nt < 8; nt++) {
            bm0 = fmaxf(bm0, fmaxf(s[nt][0], s[nt][1]));
            bm1 = fmaxf(bm1, fmaxf(s[nt][2], s[nt][3]));
        }
        bm0 = fmaxf(bm0, __shfl_xor_sync(0xffffffffu, bm0, 1));
        bm0 = fmaxf(bm0, __shfl_xor_sync(0xffffffffu, bm0, 2));
        bm1 = fmaxf(bm1, __shfl_xor_sync(0xffffffffu, bm1, 1));
        bm1 = fmaxf(bm1, __shfl_xor_sync(0xffffffffu, bm1, 2));
        const float nm0 = fmaxf(m0, bm0);
        const float nm1 = fmaxf(m1, bm1);
        const float f0 = __expf(m0 - nm0);
        const float f1 = __expf(m1 - nm1);
        float ps0 = 0.0f, ps1 = 0.0f;
        const int pr0 = (rowb + g) * 36;
        const int pr1 = pr0 + 8 * 36;
#pragma unroll
        for (int nt = 0; nt < 8; nt++) {
            float p0 = __expf(s[nt][0] - nm0);
            float p1 = __expf(s[nt][1] - nm0);
            float p2 = __expf(s[nt][2] - nm1);
            float p3 = __expf(s[nt][3] - nm1);
            ps0 += p0 + p1;
            ps1 += p2 + p3;
            Psu[pr0 + nt * 4 + t4] = h2u(p0, p1);
            Psu[pr1 + nt * 4 + t4] = h2u(p2, p3);
        }
        ps0 += __shfl_xor_sync(0xffffffffu, ps0, 1);
        ps0 += __shfl_xor_sync(0xffffffffu, ps0, 2);
        ps1 += __shfl_xor_sync(0xffffffffu, ps1, 1);
        ps1 += __shfl_xor_sync(0xffffffffu, ps1, 2);
        l0 = l0 * f0 + ps0;
        l1 = l1 * f1 + ps1;
        m0 = nm0;
        m1 = nm1;
#pragma unroll
        for (int nt = 0; nt < 16; nt++) {
            accO[nt][0] *= f0; accO[nt][1] *= f0;
            accO[nt][2] *= f1; accO[nt][3] *= f1;
        }
        __syncwarp();

#pragma unroll
        for (int ks_ = 0; ks_ < 4; ks_++) {
            uint32_t a[4];
            const int a0 = pr0 + 8 * ks_ + t4;
            const int a1 = pr1 + 8 * ks_ + t4;
            a[0] = Psu[a0];
            a[1] = Psu[a1];
            a[2] = Psu[a0 + 4];
            a[3] = Psu[a1 + 4];
#pragma unroll
            for (int nt = 0; nt < 16; nt++) {
                uint32_t b[2];
                const int vr = (nt * 8 + g) * 36 + 8 * ks_ + t4;
                b[0] = Vu[vr];
                b[1] = Vu[vr + 4];
                mma_fp16(accO[nt], a, b);
            }
        }
        __syncthreads();
        if (kb + 2 < nkb) issue(kb + 2);
        CP_COMMIT();
    }

    // ---- Normalize + write O (fp16) in [B,S,D]
    const int b_ = bh >> 4;
    const int h_ = bh & 15;
    const float inv0 = 1.0f / l0;
    const float inv1 = 1.0f / l1;
    const int r0g = q0 + rowb + g;
    __half* Op0 = O + ((size_t)b_ * Sc + r0g) * Dc + h_ * HDc;
    __half* Op1 = Op0 + (size_t)8 * Dc;
#pragma unroll
    for (int nt = 0; nt < 16; nt++) {
        const int cc = nt * 8 + 2 * t4;
        *(uint32_t*)&Op0[cc] = h2u(accO[nt][0] * inv0, accO[nt][1] * inv0);
        *(uint32_t*)&Op1[cc] = h2u(accO[nt][2] * inv1, accO[nt][3] * inv1);
    }
}

// ---------------------------------------------------------------------------
extern "C" void kernel_launch(void* const* d_in, const int* in_sizes, int n_in,
                              void* d_out, int out_size)
{
    const float* x  = (const float*)d_in[0];
    const float* wq = (const float*)d_in[1];
    const float* wk = (const float*)d_in[2];
    const float* wv = (const float*)d_in[3];
    const float* wo = (const float*)d_in[4];
    const int* pos  = (const int*)d_in[5];

    __half *xh, *wqh, *wkh, *wvh, *woh, *q, *k, *v, *oh;
    cudaGetSymbolAddress((void**)&xh,  g_xh);
    cudaGetSymbolAddress((void**)&wqh, g_wqh);
    cudaGetSymbolAddress((void**)&wkh, g_wkh);
    cudaGetSymbolAddress((void**)&wvh, g_wvh);
    cudaGetSymbolAddress((void**)&woh, g_woh);
    cudaGetSymbolAddress((void**)&q,   g_Qh);
    cudaGetSymbolAddress((void**)&k,   g_Kh);
    cudaGetSymbolAddress((void**)&v,   g_Vh);
    cudaGetSymbolAddress((void**)&oh,  g_Oh);

    // fp32 -> fp16 conversions (once)
    const int nX4 = Mc * Dc / 4;   // 4,194,304
    const int nW4 = Dc * Dc / 4;   // 1,048,576
    f2h_kernel<<<nX4 / 256, 256>>>(x,  xh,  nX4);
    f2h_kernel<<<nW4 / 256, 256>>>(wq, wqh, nW4);
    f2h_kernel<<<nW4 / 256, 256>>>(wk, wkh, nW4);
    f2h_kernel<<<nW4 / 256, 256>>>(wv, wvh, nW4);
    f2h_kernel<<<nW4 / 256, 256>>>(wo, woh, nW4);

    cudaFuncSetAttribute(gemm_fp16h<0>, cudaFuncAttributeMaxDynamicSharedMemorySize, GSMEMB);
    cudaFuncSetAttribute(gemm_fp16h<1>, cudaFuncAttributeMaxDynamicSharedMemorySize, GSMEMB);
    cudaFuncSetAttribute(gemm_fp16h<2>, cudaFuncAttributeMaxDynamicSharedMemorySize, GSMEMB);
    cudaFuncSetAttribute(gemm_fp16h<3>, cudaFuncAttributeMaxDynamicSharedMemorySize, GSMEMB);

    dim3 gg(Dc / 128, Mc / 128);  // (16, 64)
    gemm_fp16h<3><<<gg, 256, GSMEMB>>>(xh, wqh, q, pos);   // Q proj + RoPE + scale
    gemm_fp16h<2><<<gg, 256, GSMEMB>>>(xh, wkh, k, pos);   // K proj + RoPE
    gemm_fp16h<1><<<gg, 256, GSMEMB>>>(xh, wvh, v, pos);   // V proj (transposed)

    cudaFuncSetAttribute(attn_mma,
                         cudaFuncAttributeMaxDynamicSharedMemorySize, ATT_SMEMB);
    attn_mma<<<dim3(Sc / 128, Bc * Hc), 256, ATT_SMEMB>>>(q, k, v, oh);

    gemm_fp16h<0><<<gg, 256, GSMEMB>>>(oh, woh, d_out, pos);  // out proj (fp32)
}

// round 11
// speedup vs baseline: 2.1421x; 1.0278x over previous
#include <cuda_runtime.h>
#include <cuda_fp16.h>
#include <math.h>
#include <stdint.h>

// Problem dims
constexpr int Bc = 4, Sc = 2048, Dc = 2048, Hc = 16, HDc = 128;
constexpr int Mc = Bc * Sc;

// Scratch (fp16 everywhere between stages)
__device__ __half g_xh [Mc * Dc];
__device__ __half g_wqh[Dc * Dc];
__device__ __half g_wkh[Dc * Dc];
__device__ __half g_wvh[Dc * Dc];
__device__ __half g_woh[Dc * Dc];
__device__ __half g_Qh [Bc * Hc * Sc * HDc]; // [B,H,S,HD], pre-scaled 1/sqrt(HD)
__device__ __half g_Kh [Bc * Hc * Sc * HDc]; // [B,H,S,HD]
__device__ __half g_Vh [Bc * Hc * Sc * HDc]; // [B,H,HD,S] (TRANSPOSED per head)
__device__ __half g_Oh [Mc * Dc];            // attention output [B,S,D] fp16

// ---------------------------------------------------------------------------
// helpers (sm_103 base target: mma.sync + cp.async + ldmatrix only)
// ---------------------------------------------------------------------------
__device__ __forceinline__ void mma_fp16(float* d, const uint32_t* a, const uint32_t* b) {
    asm volatile(
        "mma.sync.aligned.m16n8k16.row.col.f32.f16.f16.f32 "
        "{%0,%1,%2,%3},{%4,%5,%6,%7},{%8,%9},{%0,%1,%2,%3};"
        : "+f"(d[0]), "+f"(d[1]), "+f"(d[2]), "+f"(d[3])
        : "r"(a[0]), "r"(a[1]), "r"(a[2]), "r"(a[3]), "r"(b[0]), "r"(b[1]));
}

__device__ __forceinline__ void ldsm_x4(uint32_t* r, uint32_t addr) {
    asm volatile("ldmatrix.sync.aligned.m8n8.x4.shared.b16 {%0,%1,%2,%3}, [%4];"
        : "=r"(r[0]), "=r"(r[1]), "=r"(r[2]), "=r"(r[3]) : "r"(addr));
}

__device__ __forceinline__ uint32_t h2u(float x, float y) {
    __half2 h = __float22half2_rn(make_float2(x, y));
    return *(uint32_t*)&h;
}

__device__ __forceinline__ uint32_t smem_u32(const void* p) {
    uint32_t a;
    asm("{ .reg .u64 t; cvta.to.shared.u64 t, %1; cvt.u32.u64 %0, t; }"
        : "=r"(a) : "l"(p));
    return a;
}

#define CP_ASYNC16(dst, src) \
    asm volatile("cp.async.cg.shared.global [%0], [%1], 16;" :: "r"(dst), "l"(src))
#define CP_COMMIT() asm volatile("cp.async.commit_group;" ::: "memory")
#define CP_WAIT1()  asm volatile("cp.async.wait_group 1;" ::: "memory")
#define CP_WAIT0()  asm volatile("cp.async.wait_group 0;" ::: "memory")

// ---------------------------------------------------------------------------
// fp32 -> fp16 conversion (elementwise, float4 vectorized)
// ---------------------------------------------------------------------------
__global__ void f2h_kernel(const float* __restrict__ in, __half* __restrict__ out, int n4)
{
    int i = blockIdx.x * blockDim.x + threadIdx.x;
    if (i < n4) {
        float4 v = ((const float4*)in)[i];
        uint2 o;
        o.x = h2u(v.x, v.y);
        o.y = h2u(v.z, v.w);
        ((uint2*)out)[i] = o;
    }
}

// ---------------------------------------------------------------------------
// GEMM (round-10 proven): fp16 in, m16n8k16, cp.async 3-stage, ldmatrix.
// MODE 0: plain fp32 [M,N]; 1: fp16 V transposed; 2: fp16 K+RoPE; 3: fp16 Q.
// ---------------------------------------------------------------------------
constexpr int LDSg   = 20;
constexpr int STG_U  = 2 * 128 * LDSg;
constexpr int GSMEMB = 3 * STG_U * 4;

template <int MODE>
__global__ void __launch_bounds__(256, 2)
gemm_fp16h(const __half* __restrict__ A, const __half* __restrict__ W,
           void* __restrict__ outv, const int* __restrict__ pos)
{
    extern __shared__ uint32_t smu[];
    constexpr int Kd = Dc;
    constexpr int Nd = Dc;
    const uint32_t smb = smem_u32(smu);

    const int tid  = threadIdx.x;
    const int bm   = blockIdx.y * 128;
    const int bn   = blockIdx.x * 128;
    const int wid  = tid >> 5;
    const int lane = tid & 31;
    const int wm   = (wid >> 2) * 64;
    const int wn   = (wid & 3) * 32;
    const int g    = lane >> 2;
    const int t4   = lane & 3;

    const int lrow = tid >> 2;
    const int lc4  = tid & 3;
    const __half* Ag = A + (size_t)(bm + lrow) * Kd + lc4 * 8;
    const __half* Wg = W + (size_t)(bn + lrow) * Kd + lc4 * 8;
    const uint32_t dstA = (uint32_t)(lrow * LDSg + lc4 * 4);

    auto issue_stage = [&](int s, int kt) {
        const uint32_t so = (uint32_t)(s * STG_U);
        const int ko = kt * 32;
        CP_ASYNC16(smb + (so + dstA) * 4u,                    Ag + ko);
        CP_ASYNC16(smb + (so + dstA + 64 * LDSg) * 4u,        Ag + (size_t)64 * Kd + ko);
        CP_ASYNC16(smb + (so + 2560 + dstA) * 4u,             Wg + ko);
        CP_ASYNC16(smb + (so + 2560 + dstA + 64 * LDSg) * 4u, Wg + (size_t)64 * Kd + ko);
    };

    const uint32_t aoff = (uint32_t)((wm + (lane & 7) + ((lane >> 3) & 1) * 8) * LDSg
                                     + ((lane >> 4) & 1) * 4) * 4u;
    const uint32_t boff = (uint32_t)((wn + (lane & 7) + (lane >> 4) * 8) * LDSg
                                     + ((lane >> 3) & 1) * 4) * 4u;

    float acc[4][4][4];
#pragma unroll
    for (int mt = 0; mt < 4; mt++)
#pragma unroll
        for (int nt = 0; nt < 4; nt++)
#pragma unroll
            for (int r = 0; r < 4; r++) acc[mt][nt][r] = 0.0f;

    issue_stage(0, 0); CP_COMMIT();
    issue_stage(1, 1); CP_COMMIT();

    constexpr int NKT = Kd / 32;
    for (int kt = 0; kt < NKT; kt++) {
        const int s = kt % 3;
        CP_WAIT1();
        __syncthreads();
        if (kt + 2 < NKT) issue_stage((kt + 2) % 3, kt + 2);
        CP_COMMIT();

        const uint32_t abase = smb + (uint32_t)(s * STG_U) * 4u + aoff;
        const uint32_t bbase = smb + (uint32_t)(s * STG_U + 2560) * 4u + boff;
#pragma unroll
        for (int ks = 0; ks < 2; ks++) {
            const uint32_t ko = (uint32_t)(ks * 32);
            uint32_t af[4][4], bf0[4], bf1[4];
            ldsm_x4(af[0], abase + ko);
            ldsm_x4(af[1], abase + ko + 1280u);
            ldsm_x4(af[2], abase + ko + 2560u);
            ldsm_x4(af[3], abase + ko + 3840u);
            ldsm_x4(bf0, bbase + ko);
            ldsm_x4(bf1, bbase + ko + 1280u);
#pragma unroll
            for (int mt = 0; mt < 4; mt++) {
                mma_fp16(acc[mt][0], af[mt], bf0);
                mma_fp16(acc[mt][1], af[mt], bf0 + 2);
                mma_fp16(acc[mt][2], af[mt], bf1);
                mma_fp16(acc[mt][3], af[mt], bf1 + 2);
            }
        }
    }

    const float qscale = 0.08838834764831845f;  // 1/sqrt(128)
#pragma unroll
    for (int nt = 0; nt < 4; nt++) {
        const int col = bn + wn + nt * 8 + 2 * t4;
        if (MODE == 0) {
            float* out = (float*)outv;
#pragma unroll
            for (int mt = 0; mt < 4; mt++) {
                const int r0 = bm + wm + mt * 16 + g;
                *(float2*)&out[(size_t)r0 * Nd + col] =
                    make_float2(acc[mt][nt][0], acc[mt][nt][1]);
                *(float2*)&out[(size_t)(r0 + 8) * Nd + col] =
                    make_float2(acc[mt][nt][2], acc[mt][nt][3]);
            }
        } else {
            __half* oh = (__half*)outv;
            const int h  = col >> 7;
            const int hd = col & 127;
            float invf = 0.0f;
            if (MODE >= 2)
                invf = (float)exp2(-(double)hd * (13.287712379549449 / 128.0));
#pragma unroll
            for (int mt = 0; mt < 4; mt++) {
#pragma unroll
                for (int rr = 0; rr < 2; rr++) {
                    const int m = bm + wm + mt * 16 + g + rr * 8;
                    const int b = m >> 11;
                    const int s = m & 2047;
                    float x1 = acc[mt][nt][rr * 2];
                    float x2 = acc[mt][nt][rr * 2 + 1];
                    float r1 = x1, r2 = x2;
                    if (MODE >= 2) {
                        const float ang = (float)pos[s] * invf;
                        float sn, cs;
                        sincosf(ang, &sn, &cs);
                        r1 = x1 * cs - x2 * sn;
                        r2 = x1 * sn + x2 * cs;
                    }
                    if (MODE == 3) { r1 *= qscale; r2 *= qscale; }
                    if (MODE == 1) {
                        const size_t base = ((size_t)b * Hc + h) * HDc;
                        oh[(base + hd)     * Sc + s] = __float2half_rn(r1);
                        oh[(base + hd + 1) * Sc + s] = __float2half_rn(r2);
                    } else {
                        *(uint32_t*)&oh[(((size_t)b * Hc + h) * Sc + s) * HDc + hd] =
                            h2u(r1, r2);
                    }
                }
            }
        }
    }
}

// ---------------------------------------------------------------------------
// Flash attention (causal), fp16 m16n8k16, cp.async 2-stage K/V.
// NEW: register-resident P (score-frag -> A-frag repack, no smem round trip)
//      + ldmatrix.x4 for K and V B-fragments (conflict-free, verified).
// smem (u32): stage s at s*8960: K 64x68 (4352) + VsT 128x36 (4608).
// Total 17920 u32 = 71680 B.
// ---------------------------------------------------------------------------
constexpr int KSTG_U    = 8960;
constexpr int VOFF_U    = 4352;
constexpr int ATT_SMEMB = 2 * KSTG_U * 4;   // 71680 B

__global__ void __launch_bounds__(256, 1)
attn_mma(const __half* __restrict__ Q, const __half* __restrict__ K,
         const __half* __restrict__ V, __half* __restrict__ O)
{
    extern __shared__ uint32_t smu[];
    const uint32_t smb = smem_u32(smu);

    const int tid  = threadIdx.x;
    const int wid  = tid >> 5;
    const int lane = tid & 31;
    const int g    = lane >> 2;
    const int t4   = lane & 3;
    const int qb   = (gridDim.x - 1) - blockIdx.x;   // heavy blocks first
    const int bh   = blockIdx.y;
    const int q0   = qb * 128;
    const size_t hoff = (size_t)bh * (size_t)(Sc * HDc);
    const int rowb = wid * 16;

    // ldmatrix lane mapping: matrix m = L>>3 -> nt = ntbase + (L>>4),
    // kb = (L>>3)&1, row = L&7.  Per-lane constant offsets (u32 units *4 = bytes):
    const int ntL  = lane >> 4;
    const int kbL  = (lane >> 3) & 1;
    const int rowL = lane & 7;
    const uint32_t koffL = (uint32_t)((ntL * 8 + rowL) * 68 + 4 * kbL) * 4u;
    const uint32_t voffL = (uint32_t)((ntL * 8 + rowL) * 36 + 4 * kbL) * 4u;

    // ---- Stage Q: 128 rows x 16 chunks, stride 68 u32
    {
        const __half* Qg = Q + hoff + (size_t)q0 * HDc;
#pragma unroll
        for (int p = 0; p < 8; p++) {
            int q = tid + p * 256;
            int row = q >> 4;
            int c4 = q & 15;
            CP_ASYNC16(smb + (uint32_t)(row * 68 + c4 * 4) * 4u,
                       Qg + (size_t)row * HDc + c4 * 8);
        }
        CP_COMMIT();
        CP_WAIT0();
    }
    __syncthreads();

    // ---- Extract Q fragments (m16n8k16 A): qf[ks][0..3]
    uint32_t qf[8][4];
#pragma unroll
    for (int ks = 0; ks < 8; ks++) {
        const int r0 = (rowb + g) * 68 + 8 * ks + t4;
        const int r1 = r0 + 8 * 68;
        qf[ks][0] = smu[r0];
        qf[ks][1] = smu[r1];
        qf[ks][2] = smu[r0 + 4];
        qf[ks][3] = smu[r1 + 4];
    }
    __syncthreads();

    const int nkb = 2 * qb + 2;

    auto issue = [&](int kb) {
        const int s = kb & 1;
        const __half* Kg = K + hoff + (size_t)(kb * 64) * HDc;
        const __half* Vg = V + hoff + (size_t)kb * 64;   // [HD][S] per head
        const uint32_t kbase = smb + (uint32_t)(s * KSTG_U) * 4u;
        const uint32_t vbase = kbase + (uint32_t)VOFF_U * 4u;
#pragma unroll
        for (int p = 0; p < 4; p++) {
            int q = tid + p * 256;
            int row = q >> 4;
            int c4 = q & 15;
            CP_ASYNC16(kbase + (uint32_t)(row * 68 + c4 * 4) * 4u,
                       Kg + (size_t)row * HDc + c4 * 8);
        }
#pragma unroll
        for (int p = 0; p < 4; p++) {
            int q = tid + p * 256;
            int row = q >> 3;
            int c4 = q & 7;
            CP_ASYNC16(vbase + (uint32_t)(row * 36 + c4 * 4) * 4u,
                       Vg + (size_t)row * Sc + c4 * 8);
        }
    };

    float accO[16][4];
#pragma unroll
    for (int nt = 0; nt < 16; nt++)
#pragma unroll
        for (int r = 0; r < 4; r++) accO[nt][r] = 0.0f;
    float m0 = -1e30f, m1 = -1e30f, l0 = 0.0f, l1 = 0.0f;

    issue(0); CP_COMMIT();
    if (nkb > 1) issue(1);
    CP_COMMIT();

    for (int kb = 0; kb < nkb; kb++) {
        CP_WAIT1();
        __syncthreads();
        const uint32_t kbase_b = smb + (uint32_t)((kb & 1) * KSTG_U) * 4u;
        const uint32_t vbase_b = kbase_b + (uint32_t)VOFF_U * 4u;

        // ---- Scores: warp rows [rowb, rowb+16) x 64 keys (8 n-tiles)
        float s[8][4];
#pragma unroll
        for (int nt = 0; nt < 8; nt++)
#pragma unroll
            for (int r = 0; r < 4; r++) s[nt][r] = 0.0f;

#pragma unroll
        for (int ks_ = 0; ks_ < 8; ks_++) {
#pragma unroll
            for (int ntb = 0; ntb < 8; ntb += 2) {
                uint32_t kf[4];
                ldsm_x4(kf, kbase_b + koffL + (uint32_t)(ntb * 8 * 68 + 8 * ks_) * 4u);
                mma_fp16(s[ntb],     qf[ks_], kf);
                mma_fp16(s[ntb + 1], qf[ks_], kf + 2);
            }
        }

        // ---- Causal mask (diagonal tiles only)
        if (kb >= 2 * qb) {
            const int colb = kb * 64 + 2 * t4;
            const int row0 = q0 + rowb + g;
#pragma unroll
            for (int nt = 0; nt < 8; nt++) {
                const int c0 = colb + nt * 8;
                if (c0     > row0)     s[nt][0] = -1e30f;
                if (c0 + 1 > row0)     s[nt][1] = -1e30f;
                if (c0     > row0 + 8) s[nt][2] = -1e30f;
                if (c0 + 1 > row0 + 8) s[nt][3] = -1e30f;
            }
        }

        // ---- Online softmax (rows g, g+8); P packed directly into A-frags
        float bm0 = -1e30f, bm1 = -1e30f;
#pragma unroll
        for (int nt = 0; nt < 8; nt++) {
            bm0 = fmaxf(bm0, fmaxf(s[nt][0], s[nt][1]));
            bm1 = fmaxf(bm1, fmaxf(s[nt][2], s[nt][3]));
        }
        bm0 = fmaxf(bm0, __shfl_xor_sync(0xffffffffu, bm0, 1));
        bm0 = fmaxf(bm0, __shfl_xor_sync(0xffffffffu, bm0, 2));
        bm1 = fmaxf(bm1, __shfl_xor_sync(0xffffffffu, bm1, 1));
        bm1 = fmaxf(bm1, __shfl_xor_sync(0xffffffffu, bm1, 2));
        const float nm0 = fmaxf(m0, bm0);
        const float nm1 = fmaxf(m1, bm1);
        const float f0 = __expf(m0 - nm0);
        const float f1 = __expf(m1 - nm1);
        float ps0 = 0.0f, ps1 = 0.0f;
        uint32_t pf[8][2];
#pragma unroll
        for (int nt = 0; nt < 8; nt++) {
            float p0 = __expf(s[nt][0] - nm0);
            float p1 = __expf(s[nt][1] - nm0);
            float p2 = __expf(s[nt][2] - nm1);
            float p3 = __expf(s[nt][3] - nm1);
            ps0 += p0 + p1;
            ps1 += p2 + p3;
            pf[nt][0] = h2u(p0, p1);   // row g   fragment
            pf[nt][1] = h2u(p2, p3);   // row g+8 fragment
        }
        ps0 += __shfl_xor_sync(0xffffffffu, ps0, 1);
        ps0 += __shfl_xor_sync(0xffffffffu, ps0, 2);
        ps1 += __shfl_xor_sync(0xffffffffu, ps1, 1);
        ps1 += __shfl_xor_sync(0xffffffffu, ps1, 2);
        l0 = l0 * f0 + ps0;
        l1 = l1 * f1 + ps1;
        m0 = nm0;
        m1 = nm1;
#pragma unroll
        for (int nt = 0; nt < 16; nt++) {
            accO[nt][0] *= f0; accO[nt][1] *= f0;
            accO[nt][2] *= f1; accO[nt][3] *= f1;
        }

        // ---- PV: accO += P[16x64] * V[64x128]; A from registers, B via ldsm
#pragma unroll
        for (int ks_ = 0; ks_ < 4; ks_++) {
            uint32_t a[4];
            a[0] = pf[2 * ks_][0];
            a[1] = pf[2 * ks_][1];
            a[2] = pf[2 * ks_ + 1][0];
            a[3] = pf[2 * ks_ + 1][1];
#pragma unroll
            for (int ntb = 0; ntb < 16; ntb += 2) {
                uint32_t vf[4];
                ldsm_x4(vf, vbase_b + voffL + (uint32_t)(ntb * 8 * 36 + 8 * ks_) * 4u);
                mma_fp16(accO[ntb],     a, vf);
                mma_fp16(accO[ntb + 1], a, vf + 2);
            }
        }
        __syncthreads();   // all warps done with stage (kb&1)
        if (kb + 2 < nkb) issue(kb + 2);
        CP_COMMIT();
    }

    // ---- Normalize + write O (fp16) in [B,S,D]
    const int b_ = bh >> 4;
    const int h_ = bh & 15;
    const float inv0 = 1.0f / l0;
    const float inv1 = 1.0f / l1;
    const int r0g = q0 + rowb + g;
    __half* Op0 = O + ((size_t)b_ * Sc + r0g) * Dc + h_ * HDc;
    __half* Op1 = Op0 + (size_t)8 * Dc;
#pragma unroll
    for (int nt = 0; nt < 16; nt++) {
        const int cc = nt * 8 + 2 * t4;
        *(uint32_t*)&Op0[cc] = h2u(accO[nt][0] * inv0, accO[nt][1] * inv0);
        *(uint32_t*)&Op1[cc] = h2u(accO[nt][2] * inv1, accO[nt][3] * inv1);
    }
}

// ---------------------------------------------------------------------------
extern "C" void kernel_launch(void* const* d_in, const int* in_sizes, int n_in,
                              void* d_out, int out_size)
{
    const float* x  = (const float*)d_in[0];
    const float* wq = (const float*)d_in[1];
    const float* wk = (const float*)d_in[2];
    const float* wv = (const float*)d_in[3];
    const float* wo = (const float*)d_in[4];
    const int* pos  = (const int*)d_in[5];

    __half *xh, *wqh, *wkh, *wvh, *woh, *q, *k, *v, *oh;
    cudaGetSymbolAddress((void**)&xh,  g_xh);
    cudaGetSymbolAddress((void**)&wqh, g_wqh);
    cudaGetSymbolAddress((void**)&wkh, g_wkh);
    cudaGetSymbolAddress((void**)&wvh, g_wvh);
    cudaGetSymbolAddress((void**)&woh, g_woh);
    cudaGetSymbolAddress((void**)&q,   g_Qh);
    cudaGetSymbolAddress((void**)&k,   g_Kh);
    cudaGetSymbolAddress((void**)&v,   g_Vh);
    cudaGetSymbolAddress((void**)&oh,  g_Oh);

    const int nX4 = Mc * Dc / 4;
    const int nW4 = Dc * Dc / 4;
    f2h_kernel<<<nX4 / 256, 256>>>(x,  xh,  nX4);
    f2h_kernel<<<nW4 / 256, 256>>>(wq, wqh, nW4);
    f2h_kernel<<<nW4 / 256, 256>>>(wk, wkh, nW4);
    f2h_kernel<<<nW4 / 256, 256>>>(wv, wvh, nW4);
    f2h_kernel<<<nW4 / 256, 256>>>(wo, woh, nW4);

    cudaFuncSetAttribute(gemm_fp16h<0>, cudaFuncAttributeMaxDynamicSharedMemorySize, GSMEMB);
    cudaFuncSetAttribute(gemm_fp16h<1>, cudaFuncAttributeMaxDynamicSharedMemorySize, GSMEMB);
    cudaFuncSetAttribute(gemm_fp16h<2>, cudaFuncAttributeMaxDynamicSharedMemorySize, GSMEMB);
    cudaFuncSetAttribute(gemm_fp16h<3>, cudaFuncAttributeMaxDynamicSharedMemorySize, GSMEMB);

    dim3 gg(Dc / 128, Mc / 128);  // (16, 64)
    gemm_fp16h<3><<<gg, 256, GSMEMB>>>(xh, wqh, q, pos);   // Q proj + RoPE + scale
    gemm_fp16h<2><<<gg, 256, GSMEMB>>>(xh, wkh, k, pos);   // K proj + RoPE
    gemm_fp16h<1><<<gg, 256, GSMEMB>>>(xh, wvh, v, pos);   // V proj (transposed)

    cudaFuncSetAttribute(attn_mma,
                         cudaFuncAttributeMaxDynamicSharedMemorySize, ATT_SMEMB);
    attn_mma<<<dim3(Sc / 128, Bc * Hc), 256, ATT_SMEMB>>>(q, k, v, oh);

    gemm_fp16h<0><<<gg, 256, GSMEMB>>>(oh, woh, d_out, pos);  // out proj (fp32)
}